// round 9
// baseline (speedup 1.0000x reference)
#include <cuda_runtime.h>
#include <math.h>
#include <stdint.h>

// ---------------------------------------------------------------------------
// ExpressionBert forward. tf32 mma.sync + cp.async pipelines.
// Round 9: single fused weight-prep kernel; z-batched QKV and QD/KD GEMM
// launches; residual-add fused into Wo/FFN2 GEMM epilogues (pure-LN kernel).
// Launch order places a representative gemm_pipe at ncu capture slot #5.
// ---------------------------------------------------------------------------

#define LNUM   4
#define DIM    512
#define NHEAD  4
#define DHD    128
#define FFI    128
#define SEQ    256
#define BATCH  128
#define NFEAT  6
#define TOK    (BATCH*SEQ)          // 32768
#define ROWSBH (BATCH*NHEAD*SEQ)    // 131072
#define QCOLS  384
#define DPAD   608

#define SM_SCALE 0.08838834764831845f  // 1/sqrt(128)

// ------------------------- static device scratch ---------------------------
__device__ float g_X  [TOK*DIM];
__device__ float g_Q  [TOK*DIM];
__device__ float g_K  [TOK*DIM];
__device__ float g_V  [TOK*DIM];
__device__ float g_CTX[TOK*DIM];
__device__ float g_TMP[TOK*DIM];
__device__ float g_Hb [TOK*FFI];
__device__ float g_QD [(size_t)ROWSBH*QCOLS];
__device__ float g_KD [(size_t)ROWSBH*QCOLS];
__device__ float g_dP [DPAD*DHD];

__device__ float g_WqT [LNUM*DIM*DIM];
__device__ float g_WkT [LNUM*DIM*DIM];
__device__ float g_WvT [LNUM*DIM*DIM];
__device__ float g_WoT [LNUM*DIM*DIM];
__device__ float g_WiT [LNUM*FFI*DIM];
__device__ float g_Wo2T[LNUM*DIM*FFI];

// ------------------------------ helpers -------------------------------------
__device__ __forceinline__ uint32_t smem_u32(const void* p) {
    uint32_t a;
    asm("{ .reg .u64 t; cvta.to.shared.u64 t, %1; cvt.u32.u64 %0, t; }"
        : "=r"(a) : "l"(p));
    return a;
}

__device__ __forceinline__ float gelu_exact(float x) {
    return 0.5f * x * (1.0f + erff(x * 0.70710678118654752440f));
}

__device__ __forceinline__ float tf32_rna(float f) {
    uint32_t u;
    asm("cvt.rna.tf32.f32 %0, %1;" : "=r"(u) : "f"(f));
    return __uint_as_float(u);
}

__device__ __forceinline__ void mma_tf32(float* d, const uint32_t* a,
                                         const uint32_t* b) {
    asm volatile(
        "mma.sync.aligned.m16n8k8.row.col.f32.tf32.tf32.f32 "
        "{%0,%1,%2,%3}, {%4,%5,%6,%7}, {%8,%9}, {%0,%1,%2,%3};"
        : "+f"(d[0]), "+f"(d[1]), "+f"(d[2]), "+f"(d[3])
        : "r"(a[0]), "r"(a[1]), "r"(a[2]), "r"(a[3]), "r"(b[0]), "r"(b[1]));
}

__device__ __forceinline__ void cp16(uint32_t saddr, const void* gptr) {
    asm volatile("cp.async.cg.shared.global [%0], [%1], 16;"
                 :: "r"(saddr), "l"(gptr) : "memory");
}
#define CP_COMMIT() asm volatile("cp.async.commit_group;" ::: "memory")
#define CP_WAIT1()  asm volatile("cp.async.wait_group 1;" ::: "memory")

#define SST 36
#define STAGEF 9216

#define FRAG_COMPUTE(sA, sB)                                                   \
    _Pragma("unroll")                                                          \
    for (int kk = 0; kk < 32; kk += 8) {                                       \
        uint32_t af[2][4];                                                     \
        _Pragma("unroll")                                                      \
        for (int mt = 0; mt < 2; mt++) {                                       \
            int r = mbase + mt * 16 + g;                                       \
            af[mt][0] = (sA)[r * SST + kk + t];                                \
            af[mt][1] = (sA)[(r + 8) * SST + kk + t];                          \
            af[mt][2] = (sA)[r * SST + kk + t + 4];                            \
            af[mt][3] = (sA)[(r + 8) * SST + kk + t + 4];                      \
        }                                                                      \
        uint32_t bf[8][2];                                                     \
        _Pragma("unroll")                                                      \
        for (int nt = 0; nt < 8; nt++) {                                       \
            int r = nbase + nt * 8 + g;                                        \
            bf[nt][0] = (sB)[r * SST + kk + t];                                \
            bf[nt][1] = (sB)[r * SST + kk + t + 4];                            \
        }                                                                      \
        _Pragma("unroll")                                                      \
        for (int mt = 0; mt < 2; mt++)                                         \
            _Pragma("unroll")                                                  \
            for (int nt = 0; nt < 8; nt++)                                     \
                mma_tf32(acc[mt][nt], af[mt], bf[nt]);                         \
    }

// ------------------- batched pipelined tf32 GEMM ----------------------------
// blockIdx.z selects a (A, BT, bias, R, C, mode) slot. Inner loop identical
// to the round-7/8 verified kernel. mode: 0 none, 1 QD window, 2 KD window.
// RESID: C = acc + bias + R.
struct GemmBatch {
    const float* A[3];
    const float* BT[3];
    const float* bias[3];
    const float* R[3];
    float*       C[3];
    int          mode[3];
};

template<int GELU, int RESID>
__global__ __launch_bounds__(256) void gemm_pipe(GemmBatch p, int K, int N) {
    extern __shared__ float dsm[];
    int tid  = threadIdx.x;
    int wid  = tid >> 5, lane = tid & 31;
    int g    = lane >> 2, t = lane & 3;
    int m0   = blockIdx.y * 128;
    int n0   = blockIdx.x * 128;
    int z    = blockIdx.z;
    int wm   = wid >> 1, wn = wid & 1;
    int mbase = wm * 32, nbase = wn * 64;

    const float* A    = p.A[z];
    const float* bias = p.bias[z];
    const float* R    = p.R[z];
    float*       C    = p.C[z];
    const float* Beff = p.BT[z];
    int mode = p.mode[z];
    if (mode == 1)      Beff += (size_t)((m0 & 1023) >> 2) * K;
    else if (mode == 2) Beff += (size_t)(224 - ((m0 & 1023) >> 2)) * K;

    float acc[2][8][4];
    #pragma unroll
    for (int i = 0; i < 2; i++)
        #pragma unroll
        for (int j = 0; j < 8; j++)
            #pragma unroll
            for (int q = 0; q < 4; q++) acc[i][j][q] = 0.0f;

    int nch = K >> 5;
    {
        float* sA = dsm;
        float* sB = dsm + 4608;
        #pragma unroll
        for (int i = 0; i < 4; i++) {
            int idx = tid + i * 256, row = idx >> 3, seg = idx & 7;
            cp16(smem_u32(sA + row * SST + seg * 4),
                 &A[(size_t)(m0 + row) * K + seg * 4]);
            cp16(smem_u32(sB + row * SST + seg * 4),
                 &Beff[(size_t)(n0 + row) * K + seg * 4]);
        }
        CP_COMMIT();
    }
    for (int c = 0; c < nch; c++) {
        if (c + 1 < nch) {
            float* sA = dsm + ((c + 1) & 1) * STAGEF;
            float* sB = sA + 4608;
            #pragma unroll
            for (int i = 0; i < 4; i++) {
                int idx = tid + i * 256, row = idx >> 3, seg = idx & 7;
                cp16(smem_u32(sA + row * SST + seg * 4),
                     &A[(size_t)(m0 + row) * K + (c + 1) * 32 + seg * 4]);
                cp16(smem_u32(sB + row * SST + seg * 4),
                     &Beff[(size_t)(n0 + row) * K + (c + 1) * 32 + seg * 4]);
            }
            CP_COMMIT();
        } else {
            CP_COMMIT();
        }
        CP_WAIT1();
        __syncthreads();
        const uint32_t* sA = (const uint32_t*)(dsm + (c & 1) * STAGEF);
        const uint32_t* sB = sA + 4608;
        FRAG_COMPUTE(sA, sB);
        __syncthreads();
    }

    #pragma unroll
    for (int mt = 0; mt < 2; mt++) {
        #pragma unroll
        for (int nt = 0; nt < 8; nt++) {
            int col = n0 + nbase + nt * 8 + 2 * t;
            float b0 = bias ? bias[col]     : 0.0f;
            float b1 = bias ? bias[col + 1] : 0.0f;
            int r0 = m0 + mbase + mt * 16 + g;
            int r1 = r0 + 8;
            float v00 = acc[mt][nt][0] + b0, v01 = acc[mt][nt][1] + b1;
            float v10 = acc[mt][nt][2] + b0, v11 = acc[mt][nt][3] + b1;
            if (GELU) {
                v00 = gelu_exact(v00); v01 = gelu_exact(v01);
                v10 = gelu_exact(v10); v11 = gelu_exact(v11);
            }
            if (RESID) {
                float2 x0 = *reinterpret_cast<const float2*>(&R[(size_t)r0 * N + col]);
                float2 x1 = *reinterpret_cast<const float2*>(&R[(size_t)r1 * N + col]);
                v00 += x0.x; v01 += x0.y;
                v10 += x1.x; v11 += x1.y;
            }
            *reinterpret_cast<float2*>(&C[(size_t)r0 * N + col]) = make_float2(v00, v01);
            *reinterpret_cast<float2*>(&C[(size_t)r1 * N + col]) = make_float2(v10, v11);
        }
    }
}

// ------------- fused attention: scores + softmax + ctx (verified r8) --------
#define PST 260
#define VST 132
#define OFF_Q0  0
#define OFF_Q1  4608
#define OFF_K0  9216
#define OFF_K1  18432
#define OFF_P   0
#define OFF_V0  33280
#define OFF_V1  37504
#define OFF_RED 41728
#define FUSED_SMEMF 42240

__global__ __launch_bounds__(256) void fused_attn(
    const float* __restrict__ Q, const float* __restrict__ Km,
    const float* __restrict__ V,
    const float* __restrict__ QD, const float* __restrict__ KD,
    const float* __restrict__ mask, float* __restrict__ CTX) {
    extern __shared__ float dsm[];
    int tid  = threadIdx.x;
    int wid  = tid >> 5, lane = tid & 31;
    int g    = lane >> 2, t = lane & 3;
    int l0   = blockIdx.x * 128;
    int bh   = blockIdx.y;
    int b    = bh >> 2, h = bh & 3;
    int wm   = wid >> 1, wn = wid & 1;
    int mbase = wm * 32;
    int nbase2 = wn * 64;

    const float* Qb = Q  + (size_t)b * SEQ * DIM + h * DHD;
    const float* Kb = Km + (size_t)b * SEQ * DIM + h * DHD;
    const float* Vb = V  + (size_t)b * SEQ * DIM + h * DHD;

    float acc[2][16][4];
    #pragma unroll
    for (int i = 0; i < 2; i++)
        #pragma unroll
        for (int j = 0; j < 16; j++)
            #pragma unroll
            for (int q = 0; q < 4; q++) acc[i][j][q] = 0.0f;

    {
        float* sQ = dsm + OFF_Q0;
        float* sK = dsm + OFF_K0;
        #pragma unroll
        for (int i = 0; i < 4; i++) {
            int idx = tid + i * 256, row = idx >> 3, seg = idx & 7;
            cp16(smem_u32(sQ + row * SST + seg * 4),
                 &Qb[(size_t)(l0 + row) * DIM + seg * 4]);
        }
        #pragma unroll
        for (int i = 0; i < 8; i++) {
            int idx = tid + i * 256, row = idx >> 3, seg = idx & 7;
            cp16(smem_u32(sK + row * SST + seg * 4),
                 &Kb[(size_t)row * DIM + seg * 4]);
        }
        CP_COMMIT();
    }
    for (int c = 0; c < 4; c++) {
        if (c + 1 < 4) {
            float* sQ = dsm + ((c + 1) & 1 ? OFF_Q1 : OFF_Q0);
            float* sK = dsm + ((c + 1) & 1 ? OFF_K1 : OFF_K0);
            #pragma unroll
            for (int i = 0; i < 4; i++) {
                int idx = tid + i * 256, row = idx >> 3, seg = idx & 7;
                cp16(smem_u32(sQ + row * SST + seg * 4),
                     &Qb[(size_t)(l0 + row) * DIM + (c + 1) * 32 + seg * 4]);
            }
            #pragma unroll
            for (int i = 0; i < 8; i++) {
                int idx = tid + i * 256, row = idx >> 3, seg = idx & 7;
                cp16(smem_u32(sK + row * SST + seg * 4),
                     &Kb[(size_t)row * DIM + (c + 1) * 32 + seg * 4]);
            }
            CP_COMMIT();
        } else {
            CP_COMMIT();
        }
        CP_WAIT1();
        __syncthreads();
        const uint32_t* sQ = (const uint32_t*)(dsm + ((c & 1) ? OFF_Q1 : OFF_Q0));
        const uint32_t* sK = (const uint32_t*)(dsm + ((c & 1) ? OFF_K1 : OFF_K0));
        #pragma unroll
        for (int kk = 0; kk < 32; kk += 8) {
            uint32_t af[2][4];
            #pragma unroll
            for (int mt = 0; mt < 2; mt++) {
                int r = mbase + mt * 16 + g;
                af[mt][0] = sQ[r * SST + kk + t];
                af[mt][1] = sQ[(r + 8) * SST + kk + t];
                af[mt][2] = sQ[r * SST + kk + t + 4];
                af[mt][3] = sQ[(r + 8) * SST + kk + t + 4];
            }
            #pragma unroll
            for (int nth = 0; nth < 2; nth++) {
                uint32_t bf[8][2];
                #pragma unroll
                for (int j = 0; j < 8; j++) {
                    int r = wn * 128 + nth * 64 + j * 8 + g;
                    bf[j][0] = sK[r * SST + kk + t];
                    bf[j][1] = sK[r * SST + kk + t + 4];
                }
                #pragma unroll
                for (int mt = 0; mt < 2; mt++)
                    #pragma unroll
                    for (int j = 0; j < 8; j++)
                        mma_tf32(acc[mt][nth * 8 + j], af[mt], bf[j]);
            }
        }
        __syncthreads();
    }

    #pragma unroll
    for (int mt = 0; mt < 2; mt++) {
        int ll0 = l0 + mbase + mt * 16 + g;
        int ll1 = ll0 + 8;
        size_t qdr0 = ((size_t)(b * SEQ + ll0) * NHEAD + h) * QCOLS;
        size_t qdr1 = ((size_t)(b * SEQ + ll1) * NHEAD + h) * QCOLS;
        #pragma unroll
        for (int nt = 0; nt < 16; nt++) {
            int rr0 = wn * 128 + nt * 8 + 2 * t;
            int rr1 = rr0 + 1;
            size_t kdr0 = ((size_t)(b * SEQ + rr0) * NHEAD + h) * QCOLS;
            size_t kdr1 = ((size_t)(b * SEQ + rr1) * NHEAD + h) * QCOLS;
            float bias0 = (1.0f - mask[b * SEQ + rr0]) * (-1e9f);
            float bias1 = (1.0f - mask[b * SEQ + rr1]) * (-1e9f);
            int jq00 = (ll0 & 31) + 255 - rr0, jq01 = jq00 - 1;
            int jq10 = (ll1 & 31) + 255 - rr0, jq11 = jq10 - 1;
            int jk00 = ll0 - (rr0 & 31) + 31,  jk01 = ll0 - (rr1 & 31) + 31;
            int jk10 = ll1 - (rr0 & 31) + 31,  jk11 = ll1 - (rr1 & 31) + 31;
            acc[mt][nt][0] = (acc[mt][nt][0] + QD[qdr0 + jq00] + KD[kdr0 + jk00]) * SM_SCALE + bias0;
            acc[mt][nt][1] = (acc[mt][nt][1] + QD[qdr0 + jq01] + KD[kdr1 + jk01]) * SM_SCALE + bias1;
            acc[mt][nt][2] = (acc[mt][nt][2] + QD[qdr1 + jq10] + KD[kdr0 + jk10]) * SM_SCALE + bias0;
            acc[mt][nt][3] = (acc[mt][nt][3] + QD[qdr1 + jq11] + KD[kdr1 + jk11]) * SM_SCALE + bias1;
        }
    }

    float* rmax = dsm + OFF_RED;
    float* rsum = dsm + OFF_RED + 256;
    float mx[2][2];
    #pragma unroll
    for (int mt = 0; mt < 2; mt++)
        #pragma unroll
        for (int hf = 0; hf < 2; hf++) {
            float m = -1e30f;
            #pragma unroll
            for (int nt = 0; nt < 16; nt++) {
                m = fmaxf(m, acc[mt][nt][hf * 2]);
                m = fmaxf(m, acc[mt][nt][hf * 2 + 1]);
            }
            m = fmaxf(m, __shfl_xor_sync(0xffffffffu, m, 1));
            m = fmaxf(m, __shfl_xor_sync(0xffffffffu, m, 2));
            mx[mt][hf] = m;
        }
    if (t == 0) {
        #pragma unroll
        for (int mt = 0; mt < 2; mt++)
            #pragma unroll
            for (int hf = 0; hf < 2; hf++) {
                int lrow = mbase + mt * 16 + hf * 8 + g;
                rmax[wn * 128 + lrow] = mx[mt][hf];
            }
    }
    __syncthreads();
    #pragma unroll
    for (int mt = 0; mt < 2; mt++)
        #pragma unroll
        for (int hf = 0; hf < 2; hf++) {
            int lrow = mbase + mt * 16 + hf * 8 + g;
            float m = fmaxf(rmax[lrow], rmax[128 + lrow]);
            float s = 0.0f;
            #pragma unroll
            for (int nt = 0; nt < 16; nt++) {
                float e0 = __expf(acc[mt][nt][hf * 2]     - m);
                float e1 = __expf(acc[mt][nt][hf * 2 + 1] - m);
                acc[mt][nt][hf * 2]     = e0;
                acc[mt][nt][hf * 2 + 1] = e1;
                s += e0 + e1;
            }
            s += __shfl_xor_sync(0xffffffffu, s, 1);
            s += __shfl_xor_sync(0xffffffffu, s, 2);
            if (t == 0) rsum[wn * 128 + lrow] = s;
        }
    __syncthreads();
    #pragma unroll
    for (int mt = 0; mt < 2; mt++)
        #pragma unroll
        for (int hf = 0; hf < 2; hf++) {
            int lrow = mbase + mt * 16 + hf * 8 + g;
            float inv = 1.0f / (rsum[lrow] + rsum[128 + lrow]);
            #pragma unroll
            for (int nt = 0; nt < 16; nt++) {
                acc[mt][nt][hf * 2]     *= inv;
                acc[mt][nt][hf * 2 + 1] *= inv;
            }
        }
    __syncthreads();

    float* P = dsm + OFF_P;
    #pragma unroll
    for (int mt = 0; mt < 2; mt++) {
        int lr0 = mbase + mt * 16 + g;
        int lr1 = lr0 + 8;
        #pragma unroll
        for (int nt = 0; nt < 16; nt++) {
            int col = wn * 128 + nt * 8 + 2 * t;
            *reinterpret_cast<float2*>(&P[lr0 * PST + col]) =
                make_float2(acc[mt][nt][0], acc[mt][nt][1]);
            *reinterpret_cast<float2*>(&P[lr1 * PST + col]) =
                make_float2(acc[mt][nt][2], acc[mt][nt][3]);
        }
    }
    __syncthreads();

    float acc2[2][8][4];
    #pragma unroll
    for (int i = 0; i < 2; i++)
        #pragma unroll
        for (int j = 0; j < 8; j++)
            #pragma unroll
            for (int q = 0; q < 4; q++) acc2[i][j][q] = 0.0f;

    {
        float* sV = dsm + OFF_V0;
        #pragma unroll
        for (int i = 0; i < 4; i++) {
            int idx = tid + i * 256, r = idx >> 5, dseg = idx & 31;
            cp16(smem_u32(sV + r * VST + dseg * 4),
                 &Vb[(size_t)r * DIM + dseg * 4]);
        }
        CP_COMMIT();
    }
    for (int c = 0; c < 8; c++) {
        if (c + 1 < 8) {
            float* sV = dsm + (((c + 1) & 1) ? OFF_V1 : OFF_V0);
            #pragma unroll
            for (int i = 0; i < 4; i++) {
                int idx = tid + i * 256, r = idx >> 5, dseg = idx & 31;
                cp16(smem_u32(sV + r * VST + dseg * 4),
                     &Vb[(size_t)((c + 1) * 32 + r) * DIM + dseg * 4]);
            }
            CP_COMMIT();
        } else {
            CP_COMMIT();
        }
        CP_WAIT1();
        __syncthreads();
        const uint32_t* sP = (const uint32_t*)P;
        const uint32_t* sV = (const uint32_t*)(dsm + ((c & 1) ? OFF_V1 : OFF_V0));
        #pragma unroll
        for (int kk = 0; kk < 32; kk += 8) {
            uint32_t af[2][4];
            #pragma unroll
            for (int mt = 0; mt < 2; mt++) {
                int r = mbase + mt * 16 + g;
                af[mt][0] = sP[r * PST + c * 32 + kk + t];
                af[mt][1] = sP[(r + 8) * PST + c * 32 + kk + t];
                af[mt][2] = sP[r * PST + c * 32 + kk + t + 4];
                af[mt][3] = sP[(r + 8) * PST + c * 32 + kk + t + 4];
            }
            uint32_t bf[8][2];
            #pragma unroll
            for (int nt = 0; nt < 8; nt++) {
                int d = nbase2 + nt * 8 + g;
                bf[nt][0] = sV[(kk + t) * VST + d];
                bf[nt][1] = sV[(kk + t + 4) * VST + d];
            }
            #pragma unroll
            for (int mt = 0; mt < 2; mt++)
                #pragma unroll
                for (int nt = 0; nt < 8; nt++)
                    mma_tf32(acc2[mt][nt], af[mt], bf[nt]);
        }
        __syncthreads();
    }

    #pragma unroll
    for (int mt = 0; mt < 2; mt++) {
        #pragma unroll
        for (int nt = 0; nt < 8; nt++) {
            int col = nbase2 + nt * 8 + 2 * t;
            int rr0 = l0 + mbase + mt * 16 + g;
            int rr1 = rr0 + 8;
            float* dst0 = &CTX[(size_t)(b * SEQ + rr0) * DIM + h * DHD + col];
            float* dst1 = &CTX[(size_t)(b * SEQ + rr1) * DIM + h * DHD + col];
            *reinterpret_cast<float2*>(dst0) = make_float2(acc2[mt][nt][0], acc2[mt][nt][1]);
            *reinterpret_cast<float2*>(dst1) = make_float2(acc2[mt][nt][2], acc2[mt][nt][3]);
        }
    }
}

// ---------------- fused weight prep: all transposes + dist pad --------------
// grid (4096, 1, 7): z 0..3 = Wq/Wk/Wv/Wo (LNUM*DIM*DIM each), z=4 Wi,
// z=5 Wo2, z=6 dist pad.
__global__ void wprep(const float* __restrict__ Wq, const float* __restrict__ Wk,
                      const float* __restrict__ Wv, const float* __restrict__ Wo,
                      const float* __restrict__ Wi, const float* __restrict__ Wo2,
                      const float* __restrict__ dist,
                      float* __restrict__ WqT, float* __restrict__ WkT,
                      float* __restrict__ WvT, float* __restrict__ WoT,
                      float* __restrict__ WiT, float* __restrict__ Wo2T,
                      float* __restrict__ dPp) {
    int z = blockIdx.z;
    int i = blockIdx.x * 256 + threadIdx.x;
    if (z < 4) {                         // 4*262144 elems, grid.x covers exactly
        const float* S = (z == 0) ? Wq : (z == 1) ? Wk : (z == 2) ? Wv : Wo;
        float* D       = (z == 0) ? WqT : (z == 1) ? WkT : (z == 2) ? WvT : WoT;
        int l = i >> 18;
        int w = i & 262143;
        int k = w >> 9, n = w & 511;
        D[(size_t)l * 262144 + n * 512 + k] = tf32_rna(S[i]);
    } else if (z == 4) {                 // Wi [L,512,128] -> WiT [L,128,512]
        if (i < LNUM * DIM * FFI) {
            int l = i >> 16, w = i & 65535;
            int k = w >> 7, n = w & 127;
            WiT[(size_t)l * 65536 + n * 512 + k] = tf32_rna(Wi[i]);
        }
    } else if (z == 5) {                 // Wo2 [L,128,512] -> Wo2T [L,512,128]
        if (i < LNUM * FFI * DIM) {
            int l = i >> 16, w = i & 65535;
            int k = w >> 9, n = w & 511;
            Wo2T[(size_t)l * 65536 + n * 128 + k] = tf32_rna(Wo2[i]);
        }
    } else {                             // dist pad
        if (i < DPAD * DHD) {
            int pp = i >> 7;
            dPp[i] = (pp < 511) ? tf32_rna(dist[i]) : 0.0f;
        }
    }
}

// --------------------------- embedding + LN ---------------------------------
__device__ __forceinline__ void block_reduce2(float& a, float& b) {
    __shared__ float sa[8], sb[8];
    int lane = threadIdx.x & 31, w = threadIdx.x >> 5;
    #pragma unroll
    for (int o = 16; o; o >>= 1) {
        a += __shfl_xor_sync(0xffffffffu, a, o);
        b += __shfl_xor_sync(0xffffffffu, b, o);
    }
    if (lane == 0) { sa[w] = a; sb[w] = b; }
    __syncthreads();
    if (w == 0) {
        a = (lane < 8) ? sa[lane] : 0.0f;
        b = (lane < 8) ? sb[lane] : 0.0f;
        #pragma unroll
        for (int o = 4; o; o >>= 1) {
            a += __shfl_xor_sync(0xffffffffu, a, o);
            b += __shfl_xor_sync(0xffffffffu, b, o);
        }
        if (lane == 0) { sa[0] = a; sb[0] = b; }
    }
    __syncthreads();
    a = sa[0]; b = sb[0];
}

__global__ void embed_ln(const int* __restrict__ ids, const float* __restrict__ inW,
                         const float* __restrict__ inb, const float* __restrict__ tok,
                         const float* __restrict__ g,  const float* __restrict__ bb,
                         float* __restrict__ X) {
    int tt = blockIdx.x, tid = threadIdx.x;
    float f[NFEAT];
    #pragma unroll
    for (int i = 0; i < NFEAT; i++) f[i] = (float)ids[tt * NFEAT + i];
    int d0 = tid, d1 = tid + 256;
    float v0 = inb[d0] + tok[d0];
    float v1 = inb[d1] + tok[d1];
    #pragma unroll
    for (int i = 0; i < NFEAT; i++) {
        v0 += f[i] * inW[i * DIM + d0];
        v1 += f[i] * inW[i * DIM + d1];
    }
    float s = v0 + v1, q = v0 * v0 + v1 * v1;
    block_reduce2(s, q);
    float mu  = s * (1.0f / DIM);
    float var = q * (1.0f / DIM) - mu * mu;
    float r   = rsqrtf(var + 1e-12f);
    size_t base = (size_t)tt * DIM;
    X[base + d0] = (v0 - mu) * r * g[d0] + bb[d0];
    X[base + d1] = (v1 - mu) * r * g[d1] + bb[d1];
}

// warp-per-token pure LayerNorm (input already has residual added)
__global__ __launch_bounds__(256) void ln_w(
    const float* __restrict__ in,
    const float* __restrict__ g, const float* __restrict__ bb,
    float* __restrict__ out) {
    int wid = threadIdx.x >> 5, lane = threadIdx.x & 31;
    int tt = blockIdx.x * 8 + wid;
    size_t base = (size_t)tt * DIM;
    float4 v[4];
    float s = 0.0f, q = 0.0f;
    #pragma unroll
    for (int i = 0; i < 4; i++) {
        int col = i * 128 + lane * 4;
        v[i] = *reinterpret_cast<const float4*>(&in[base + col]);
        s += v[i].x + v[i].y + v[i].z + v[i].w;
        q += v[i].x * v[i].x + v[i].y * v[i].y + v[i].z * v[i].z + v[i].w * v[i].w;
    }
    #pragma unroll
    for (int o = 16; o; o >>= 1) {
        s += __shfl_xor_sync(0xffffffffu, s, o);
        q += __shfl_xor_sync(0xffffffffu, q, o);
    }
    float mu  = s * (1.0f / DIM);
    float var = q * (1.0f / DIM) - mu * mu;
    float r   = rsqrtf(var + 1e-12f);
    #pragma unroll
    for (int i = 0; i < 4; i++) {
        int col = i * 128 + lane * 4;
        float4 g4 = *reinterpret_cast<const float4*>(&g[col]);
        float4 b4 = *reinterpret_cast<const float4*>(&bb[col]);
        float4 o4;
        o4.x = (v[i].x - mu) * r * g4.x + b4.x;
        o4.y = (v[i].y - mu) * r * g4.y + b4.y;
        o4.z = (v[i].z - mu) * r * g4.z + b4.z;
        o4.w = (v[i].w - mu) * r * g4.w + b4.w;
        *reinterpret_cast<float4*>(&out[base + col]) = o4;
    }
}

// ------------------------------ host driver ----------------------------------
extern "C" void kernel_launch(void* const* d_in, const int* in_sizes, int n_in,
                              void* d_out, int out_size) {
    (void)in_sizes; (void)n_in; (void)out_size;
    const int*   ids  = (const int*)  d_in[0];
    const float* mask = (const float*)d_in[1];
    const float* inW  = (const float*)d_in[2];
    const float* inb  = (const float*)d_in[3];
    const float* tok  = (const float*)d_in[4];
    const float* elg  = (const float*)d_in[5];
    const float* elb  = (const float*)d_in[6];
    const float* dist = (const float*)d_in[7];
    const float* Wq   = (const float*)d_in[8];
    const float* bq   = (const float*)d_in[9];
    const float* Wk   = (const float*)d_in[10];
    const float* bk   = (const float*)d_in[11];
    const float* Wv   = (const float*)d_in[12];
    const float* bv   = (const float*)d_in[13];
    const float* Wo   = (const float*)d_in[14];
    const float* bo   = (const float*)d_in[15];
    const float* ln1g = (const float*)d_in[16];
    const float* ln1b = (const float*)d_in[17];
    const float* Wi   = (const float*)d_in[18];
    const float* bi   = (const float*)d_in[19];
    const float* Wo2  = (const float*)d_in[20];
    const float* bo2  = (const float*)d_in[21];
    const float* ln2g = (const float*)d_in[22];
    const float* ln2b = (const float*)d_in[23];
    float* out = (float*)d_out;

    float *X, *Q, *Kb, *V, *CTX, *TMP, *Hb, *QD, *KD, *dP;
    float *WqT, *WkT, *WvT, *WoT, *WiT, *Wo2T;
    cudaGetSymbolAddress((void**)&X,    g_X);
    cudaGetSymbolAddress((void**)&Q,    g_Q);
    cudaGetSymbolAddress((void**)&Kb,   g_K);
    cudaGetSymbolAddress((void**)&V,    g_V);
    cudaGetSymbolAddress((void**)&CTX,  g_CTX);
    cudaGetSymbolAddress((void**)&TMP,  g_TMP);
    cudaGetSymbolAddress((void**)&Hb,   g_Hb);
    cudaGetSymbolAddress((void**)&QD,   g_QD);
    cudaGetSymbolAddress((void**)&KD,   g_KD);
    cudaGetSymbolAddress((void**)&dP,   g_dP);
    cudaGetSymbolAddress((void**)&WqT,  g_WqT);
    cudaGetSymbolAddress((void**)&WkT,  g_WkT);
    cudaGetSymbolAddress((void**)&WvT,  g_WvT);
    cudaGetSymbolAddress((void**)&WoT,  g_WoT);
    cudaGetSymbolAddress((void**)&WiT,  g_WiT);
    cudaGetSymbolAddress((void**)&Wo2T, g_Wo2T);

    const int GEMM_SMEM  = 2 * STAGEF * 4;
    const int FUSED_SMEM = FUSED_SMEMF * 4;
    cudaFuncSetAttribute(gemm_pipe<0,0>, cudaFuncAttributeMaxDynamicSharedMemorySize, GEMM_SMEM);
    cudaFuncSetAttribute(gemm_pipe<1,0>, cudaFuncAttributeMaxDynamicSharedMemorySize, GEMM_SMEM);
    cudaFuncSetAttribute(gemm_pipe<0,1>, cudaFuncAttributeMaxDynamicSharedMemorySize, GEMM_SMEM);
    cudaFuncSetAttribute(fused_attn,     cudaFuncAttributeMaxDynamicSharedMemorySize, FUSED_SMEM);

    // launch 0: all weight prep
    wprep<<<dim3(4096, 1, 7), 256>>>(Wq, Wk, Wv, Wo, Wi, Wo2, dist,
                                     WqT, WkT, WvT, WoT, WiT, Wo2T, dP);
    // launch 1: embedding
    embed_ln<<<TOK, 256>>>(ids, inW, inb, tok, elg, elb, X);

    dim3 gQKV(DIM / 128, TOK / 128, 3);
    dim3 gG(DIM / 128, TOK / 128, 1);
    dim3 gGi(FFI / 128, TOK / 128, 1);
    dim3 gQD(QCOLS / 128, ROWSBH / 128, 2);
    dim3 gA(SEQ / 128, BATCH * NHEAD);

    for (int l = 0; l < LNUM; l++) {
        const float* wqt  = WqT  + (size_t)l * DIM * DIM;
        const float* wkt  = WkT  + (size_t)l * DIM * DIM;
        const float* wvt  = WvT  + (size_t)l * DIM * DIM;
        const float* wot  = WoT  + (size_t)l * DIM * DIM;
        const float* wit  = WiT  + (size_t)l * FFI * DIM;
        const float* wo2t = Wo2T + (size_t)l * DIM * FFI;

        GemmBatch pqkv = {};
        pqkv.A[0] = X;   pqkv.A[1] = X;   pqkv.A[2] = X;
        pqkv.BT[0] = wqt; pqkv.BT[1] = wkt; pqkv.BT[2] = wvt;
        pqkv.bias[0] = bq + l * DIM; pqkv.bias[1] = bk + l * DIM; pqkv.bias[2] = bv + l * DIM;
        pqkv.C[0] = Q;   pqkv.C[1] = Kb;  pqkv.C[2] = V;
        gemm_pipe<0,0><<<gQKV, 256, GEMM_SMEM>>>(pqkv, DIM, DIM);

        GemmBatch pqd = {};
        pqd.A[0] = Q;  pqd.A[1] = Kb;
        pqd.BT[0] = dP; pqd.BT[1] = dP;
        pqd.C[0] = QD; pqd.C[1] = KD;
        pqd.mode[0] = 1; pqd.mode[1] = 2;
        gemm_pipe<0,0><<<gQD, 256, GEMM_SMEM>>>(pqd, DHD, QCOLS);

        fused_attn<<<gA, 256, FUSED_SMEM>>>(Q, Kb, V, QD, KD, mask, CTX);

        GemmBatch pwo = {};
        pwo.A[0] = CTX; pwo.BT[0] = wot; pwo.bias[0] = bo + l * DIM;
        pwo.R[0] = X;   pwo.C[0] = TMP;
        gemm_pipe<0,1><<<gG, 256, GEMM_SMEM>>>(pwo, DIM, DIM);
        ln_w<<<TOK / 8, 256>>>(TMP, ln1g + l * DIM, ln1b + l * DIM, X);

        GemmBatch pff1 = {};
        pff1.A[0] = X; pff1.BT[0] = wit; pff1.bias[0] = bi + l * FFI; pff1.C[0] = Hb;
        gemm_pipe<1,0><<<gGi, 256, GEMM_SMEM>>>(pff1, DIM, FFI);

        GemmBatch pff2 = {};
        pff2.A[0] = Hb; pff2.BT[0] = wo2t; pff2.bias[0] = bo2 + l * DIM;
        pff2.R[0] = X;  pff2.C[0] = TMP;
        gemm_pipe<0,1><<<gG, 256, GEMM_SMEM>>>(pff2, FFI, DIM);
        ln_w<<<TOK / 8, 256>>>(TMP, ln2g + l * DIM, ln2b + l * DIM,
                               (l == LNUM - 1) ? out : X);
    }
}

// round 10
// speedup vs baseline: 1.1788x; 1.1788x over previous
#include <cuda_runtime.h>
#include <math.h>
#include <stdint.h>

// ---------------------------------------------------------------------------
// ExpressionBert forward. tf32 mma.sync + cp.async pipelines.
// Round 10: revert z-batching (register bloat -> 1 CTA/SM, occ 12.4%);
// separate template-MODE launches + __launch_bounds__(256,2) to force
// 2 CTAs/SM (regs<=128). Keep wprep fusion, residual-fused epilogues, ln_w.
// ---------------------------------------------------------------------------

#define LNUM   4
#define DIM    512
#define NHEAD  4
#define DHD    128
#define FFI    128
#define SEQ    256
#define BATCH  128
#define NFEAT  6
#define TOK    (BATCH*SEQ)          // 32768
#define ROWSBH (BATCH*NHEAD*SEQ)    // 131072
#define QCOLS  384
#define DPAD   608

#define SM_SCALE 0.08838834764831845f  // 1/sqrt(128)

// ------------------------- static device scratch ---------------------------
__device__ float g_X  [TOK*DIM];
__device__ float g_Q  [TOK*DIM];
__device__ float g_K  [TOK*DIM];
__device__ float g_V  [TOK*DIM];
__device__ float g_CTX[TOK*DIM];
__device__ float g_TMP[TOK*DIM];
__device__ float g_Hb [TOK*FFI];
__device__ float g_QD [(size_t)ROWSBH*QCOLS];
__device__ float g_KD [(size_t)ROWSBH*QCOLS];
__device__ float g_dP [DPAD*DHD];

__device__ float g_WqT [LNUM*DIM*DIM];
__device__ float g_WkT [LNUM*DIM*DIM];
__device__ float g_WvT [LNUM*DIM*DIM];
__device__ float g_WoT [LNUM*DIM*DIM];
__device__ float g_WiT [LNUM*FFI*DIM];
__device__ float g_Wo2T[LNUM*DIM*FFI];

// ------------------------------ helpers -------------------------------------
__device__ __forceinline__ uint32_t smem_u32(const void* p) {
    uint32_t a;
    asm("{ .reg .u64 t; cvta.to.shared.u64 t, %1; cvt.u32.u64 %0, t; }"
        : "=r"(a) : "l"(p));
    return a;
}

__device__ __forceinline__ float gelu_exact(float x) {
    return 0.5f * x * (1.0f + erff(x * 0.70710678118654752440f));
}

__device__ __forceinline__ float tf32_rna(float f) {
    uint32_t u;
    asm("cvt.rna.tf32.f32 %0, %1;" : "=r"(u) : "f"(f));
    return __uint_as_float(u);
}

__device__ __forceinline__ void mma_tf32(float* d, const uint32_t* a,
                                         const uint32_t* b) {
    asm volatile(
        "mma.sync.aligned.m16n8k8.row.col.f32.tf32.tf32.f32 "
        "{%0,%1,%2,%3}, {%4,%5,%6,%7}, {%8,%9}, {%0,%1,%2,%3};"
        : "+f"(d[0]), "+f"(d[1]), "+f"(d[2]), "+f"(d[3])
        : "r"(a[0]), "r"(a[1]), "r"(a[2]), "r"(a[3]), "r"(b[0]), "r"(b[1]));
}

__device__ __forceinline__ void cp16(uint32_t saddr, const void* gptr) {
    asm volatile("cp.async.cg.shared.global [%0], [%1], 16;"
                 :: "r"(saddr), "l"(gptr) : "memory");
}
#define CP_COMMIT() asm volatile("cp.async.commit_group;" ::: "memory")
#define CP_WAIT1()  asm volatile("cp.async.wait_group 1;" ::: "memory")

#define SST 36
#define STAGEF 9216

#define FRAG_COMPUTE(sA, sB)                                                   \
    _Pragma("unroll")                                                          \
    for (int kk = 0; kk < 32; kk += 8) {                                       \
        uint32_t af[2][4];                                                     \
        _Pragma("unroll")                                                      \
        for (int mt = 0; mt < 2; mt++) {                                       \
            int r = mbase + mt * 16 + g;                                       \
            af[mt][0] = (sA)[r * SST + kk + t];                                \
            af[mt][1] = (sA)[(r + 8) * SST + kk + t];                          \
            af[mt][2] = (sA)[r * SST + kk + t + 4];                            \
            af[mt][3] = (sA)[(r + 8) * SST + kk + t + 4];                      \
        }                                                                      \
        uint32_t bf[8][2];                                                     \
        _Pragma("unroll")                                                      \
        for (int nt = 0; nt < 8; nt++) {                                       \
            int r = nbase + nt * 8 + g;                                        \
            bf[nt][0] = (sB)[r * SST + kk + t];                                \
            bf[nt][1] = (sB)[r * SST + kk + t + 4];                            \
        }                                                                      \
        _Pragma("unroll")                                                      \
        for (int mt = 0; mt < 2; mt++)                                         \
            _Pragma("unroll")                                                  \
            for (int nt = 0; nt < 8; nt++)                                     \
                mma_tf32(acc[mt][nt], af[mt], bf[nt]);                         \
    }

// ---------------- pipelined tf32 GEMM (round-8 structure) -------------------
// C = A @ Beff^T + bias (+GELU) (+R residual). MODE 0 plain, 1 QD window,
// 2 KD window. __launch_bounds__(256,2): cap regs at 128 -> 2 CTAs/SM.
template<int GELU, int MODE, int RESID>
__global__ __launch_bounds__(256, 2) void gemm_pipe(
    const float* __restrict__ A, const float* __restrict__ BT,
    const float* __restrict__ bias, const float* __restrict__ R,
    float* __restrict__ C, int K, int N) {
    extern __shared__ float dsm[];
    int tid  = threadIdx.x;
    int wid  = tid >> 5, lane = tid & 31;
    int g    = lane >> 2, t = lane & 3;
    int m0   = blockIdx.y * 128;
    int n0   = blockIdx.x * 128;
    int wm   = wid >> 1, wn = wid & 1;
    int mbase = wm * 32, nbase = wn * 64;

    const float* Beff = BT;
    if (MODE == 1) Beff = BT + (size_t)((m0 & 1023) >> 2) * K;
    if (MODE == 2) Beff = BT + (size_t)(224 - ((m0 & 1023) >> 2)) * K;

    float acc[2][8][4];
    #pragma unroll
    for (int i = 0; i < 2; i++)
        #pragma unroll
        for (int j = 0; j < 8; j++)
            #pragma unroll
            for (int q = 0; q < 4; q++) acc[i][j][q] = 0.0f;

    int nch = K >> 5;
    {
        float* sA = dsm;
        float* sB = dsm + 4608;
        #pragma unroll
        for (int i = 0; i < 4; i++) {
            int idx = tid + i * 256, row = idx >> 3, seg = idx & 7;
            cp16(smem_u32(sA + row * SST + seg * 4),
                 &A[(size_t)(m0 + row) * K + seg * 4]);
            cp16(smem_u32(sB + row * SST + seg * 4),
                 &Beff[(size_t)(n0 + row) * K + seg * 4]);
        }
        CP_COMMIT();
    }
    for (int c = 0; c < nch; c++) {
        if (c + 1 < nch) {
            float* sA = dsm + ((c + 1) & 1) * STAGEF;
            float* sB = sA + 4608;
            #pragma unroll
            for (int i = 0; i < 4; i++) {
                int idx = tid + i * 256, row = idx >> 3, seg = idx & 7;
                cp16(smem_u32(sA + row * SST + seg * 4),
                     &A[(size_t)(m0 + row) * K + (c + 1) * 32 + seg * 4]);
                cp16(smem_u32(sB + row * SST + seg * 4),
                     &Beff[(size_t)(n0 + row) * K + (c + 1) * 32 + seg * 4]);
            }
            CP_COMMIT();
        } else {
            CP_COMMIT();
        }
        CP_WAIT1();
        __syncthreads();
        const uint32_t* sA = (const uint32_t*)(dsm + (c & 1) * STAGEF);
        const uint32_t* sB = sA + 4608;
        FRAG_COMPUTE(sA, sB);
        __syncthreads();
    }

    #pragma unroll
    for (int mt = 0; mt < 2; mt++) {
        #pragma unroll
        for (int nt = 0; nt < 8; nt++) {
            int col = n0 + nbase + nt * 8 + 2 * t;
            float b0 = bias ? bias[col]     : 0.0f;
            float b1 = bias ? bias[col + 1] : 0.0f;
            int r0 = m0 + mbase + mt * 16 + g;
            int r1 = r0 + 8;
            float v00 = acc[mt][nt][0] + b0, v01 = acc[mt][nt][1] + b1;
            float v10 = acc[mt][nt][2] + b0, v11 = acc[mt][nt][3] + b1;
            if (GELU) {
                v00 = gelu_exact(v00); v01 = gelu_exact(v01);
                v10 = gelu_exact(v10); v11 = gelu_exact(v11);
            }
            if (RESID) {
                float2 x0 = *reinterpret_cast<const float2*>(&R[(size_t)r0 * N + col]);
                float2 x1 = *reinterpret_cast<const float2*>(&R[(size_t)r1 * N + col]);
                v00 += x0.x; v01 += x0.y;
                v10 += x1.x; v11 += x1.y;
            }
            *reinterpret_cast<float2*>(&C[(size_t)r0 * N + col]) = make_float2(v00, v01);
            *reinterpret_cast<float2*>(&C[(size_t)r1 * N + col]) = make_float2(v10, v11);
        }
    }
}

// ------------- fused attention: scores + softmax + ctx (verified r8) --------
#define PST 260
#define VST 132
#define OFF_Q0  0
#define OFF_Q1  4608
#define OFF_K0  9216
#define OFF_K1  18432
#define OFF_P   0
#define OFF_V0  33280
#define OFF_V1  37504
#define OFF_RED 41728
#define FUSED_SMEMF 42240

__global__ __launch_bounds__(256) void fused_attn(
    const float* __restrict__ Q, const float* __restrict__ Km,
    const float* __restrict__ V,
    const float* __restrict__ QD, const float* __restrict__ KD,
    const float* __restrict__ mask, float* __restrict__ CTX) {
    extern __shared__ float dsm[];
    int tid  = threadIdx.x;
    int wid  = tid >> 5, lane = tid & 31;
    int g    = lane >> 2, t = lane & 3;
    int l0   = blockIdx.x * 128;
    int bh   = blockIdx.y;
    int b    = bh >> 2, h = bh & 3;
    int wm   = wid >> 1, wn = wid & 1;
    int mbase = wm * 32;
    int nbase2 = wn * 64;

    const float* Qb = Q  + (size_t)b * SEQ * DIM + h * DHD;
    const float* Kb = Km + (size_t)b * SEQ * DIM + h * DHD;
    const float* Vb = V  + (size_t)b * SEQ * DIM + h * DHD;

    float acc[2][16][4];
    #pragma unroll
    for (int i = 0; i < 2; i++)
        #pragma unroll
        for (int j = 0; j < 16; j++)
            #pragma unroll
            for (int q = 0; q < 4; q++) acc[i][j][q] = 0.0f;

    {
        float* sQ = dsm + OFF_Q0;
        float* sK = dsm + OFF_K0;
        #pragma unroll
        for (int i = 0; i < 4; i++) {
            int idx = tid + i * 256, row = idx >> 3, seg = idx & 7;
            cp16(smem_u32(sQ + row * SST + seg * 4),
                 &Qb[(size_t)(l0 + row) * DIM + seg * 4]);
        }
        #pragma unroll
        for (int i = 0; i < 8; i++) {
            int idx = tid + i * 256, row = idx >> 3, seg = idx & 7;
            cp16(smem_u32(sK + row * SST + seg * 4),
                 &Kb[(size_t)row * DIM + seg * 4]);
        }
        CP_COMMIT();
    }
    for (int c = 0; c < 4; c++) {
        if (c + 1 < 4) {
            float* sQ = dsm + ((c + 1) & 1 ? OFF_Q1 : OFF_Q0);
            float* sK = dsm + ((c + 1) & 1 ? OFF_K1 : OFF_K0);
            #pragma unroll
            for (int i = 0; i < 4; i++) {
                int idx = tid + i * 256, row = idx >> 3, seg = idx & 7;
                cp16(smem_u32(sQ + row * SST + seg * 4),
                     &Qb[(size_t)(l0 + row) * DIM + (c + 1) * 32 + seg * 4]);
            }
            #pragma unroll
            for (int i = 0; i < 8; i++) {
                int idx = tid + i * 256, row = idx >> 3, seg = idx & 7;
                cp16(smem_u32(sK + row * SST + seg * 4),
                     &Kb[(size_t)row * DIM + (c + 1) * 32 + seg * 4]);
            }
            CP_COMMIT();
        } else {
            CP_COMMIT();
        }
        CP_WAIT1();
        __syncthreads();
        const uint32_t* sQ = (const uint32_t*)(dsm + ((c & 1) ? OFF_Q1 : OFF_Q0));
        const uint32_t* sK = (const uint32_t*)(dsm + ((c & 1) ? OFF_K1 : OFF_K0));
        #pragma unroll
        for (int kk = 0; kk < 32; kk += 8) {
            uint32_t af[2][4];
            #pragma unroll
            for (int mt = 0; mt < 2; mt++) {
                int r = mbase + mt * 16 + g;
                af[mt][0] = sQ[r * SST + kk + t];
                af[mt][1] = sQ[(r + 8) * SST + kk + t];
                af[mt][2] = sQ[r * SST + kk + t + 4];
                af[mt][3] = sQ[(r + 8) * SST + kk + t + 4];
            }
            #pragma unroll
            for (int nth = 0; nth < 2; nth++) {
                uint32_t bf[8][2];
                #pragma unroll
                for (int j = 0; j < 8; j++) {
                    int r = wn * 128 + nth * 64 + j * 8 + g;
                    bf[j][0] = sK[r * SST + kk + t];
                    bf[j][1] = sK[r * SST + kk + t + 4];
                }
                #pragma unroll
                for (int mt = 0; mt < 2; mt++)
                    #pragma unroll
                    for (int j = 0; j < 8; j++)
                        mma_tf32(acc[mt][nth * 8 + j], af[mt], bf[j]);
            }
        }
        __syncthreads();
    }

    #pragma unroll
    for (int mt = 0; mt < 2; mt++) {
        int ll0 = l0 + mbase + mt * 16 + g;
        int ll1 = ll0 + 8;
        size_t qdr0 = ((size_t)(b * SEQ + ll0) * NHEAD + h) * QCOLS;
        size_t qdr1 = ((size_t)(b * SEQ + ll1) * NHEAD + h) * QCOLS;
        #pragma unroll
        for (int nt = 0; nt < 16; nt++) {
            int rr0 = wn * 128 + nt * 8 + 2 * t;
            int rr1 = rr0 + 1;
            size_t kdr0 = ((size_t)(b * SEQ + rr0) * NHEAD + h) * QCOLS;
            size_t kdr1 = ((size_t)(b * SEQ + rr1) * NHEAD + h) * QCOLS;
            float bias0 = (1.0f - mask[b * SEQ + rr0]) * (-1e9f);
            float bias1 = (1.0f - mask[b * SEQ + rr1]) * (-1e9f);
            int jq00 = (ll0 & 31) + 255 - rr0, jq01 = jq00 - 1;
            int jq10 = (ll1 & 31) + 255 - rr0, jq11 = jq10 - 1;
            int jk00 = ll0 - (rr0 & 31) + 31,  jk01 = ll0 - (rr1 & 31) + 31;
            int jk10 = ll1 - (rr0 & 31) + 31,  jk11 = ll1 - (rr1 & 31) + 31;
            acc[mt][nt][0] = (acc[mt][nt][0] + QD[qdr0 + jq00] + KD[kdr0 + jk00]) * SM_SCALE + bias0;
            acc[mt][nt][1] = (acc[mt][nt][1] + QD[qdr0 + jq01] + KD[kdr1 + jk01]) * SM_SCALE + bias1;
            acc[mt][nt][2] = (acc[mt][nt][2] + QD[qdr1 + jq10] + KD[kdr0 + jk10]) * SM_SCALE + bias0;
            acc[mt][nt][3] = (acc[mt][nt][3] + QD[qdr1 + jq11] + KD[kdr1 + jk11]) * SM_SCALE + bias1;
        }
    }

    float* rmax = dsm + OFF_RED;
    float* rsum = dsm + OFF_RED + 256;
    float mx[2][2];
    #pragma unroll
    for (int mt = 0; mt < 2; mt++)
        #pragma unroll
        for (int hf = 0; hf < 2; hf++) {
            float m = -1e30f;
            #pragma unroll
            for (int nt = 0; nt < 16; nt++) {
                m = fmaxf(m, acc[mt][nt][hf * 2]);
                m = fmaxf(m, acc[mt][nt][hf * 2 + 1]);
            }
            m = fmaxf(m, __shfl_xor_sync(0xffffffffu, m, 1));
            m = fmaxf(m, __shfl_xor_sync(0xffffffffu, m, 2));
            mx[mt][hf] = m;
        }
    if (t == 0) {
        #pragma unroll
        for (int mt = 0; mt < 2; mt++)
            #pragma unroll
            for (int hf = 0; hf < 2; hf++) {
                int lrow = mbase + mt * 16 + hf * 8 + g;
                rmax[wn * 128 + lrow] = mx[mt][hf];
            }
    }
    __syncthreads();
    #pragma unroll
    for (int mt = 0; mt < 2; mt++)
        #pragma unroll
        for (int hf = 0; hf < 2; hf++) {
            int lrow = mbase + mt * 16 + hf * 8 + g;
            float m = fmaxf(rmax[lrow], rmax[128 + lrow]);
            float s = 0.0f;
            #pragma unroll
            for (int nt = 0; nt < 16; nt++) {
                float e0 = __expf(acc[mt][nt][hf * 2]     - m);
                float e1 = __expf(acc[mt][nt][hf * 2 + 1] - m);
                acc[mt][nt][hf * 2]     = e0;
                acc[mt][nt][hf * 2 + 1] = e1;
                s += e0 + e1;
            }
            s += __shfl_xor_sync(0xffffffffu, s, 1);
            s += __shfl_xor_sync(0xffffffffu, s, 2);
            if (t == 0) rsum[wn * 128 + lrow] = s;
        }
    __syncthreads();
    #pragma unroll
    for (int mt = 0; mt < 2; mt++)
        #pragma unroll
        for (int hf = 0; hf < 2; hf++) {
            int lrow = mbase + mt * 16 + hf * 8 + g;
            float inv = 1.0f / (rsum[lrow] + rsum[128 + lrow]);
            #pragma unroll
            for (int nt = 0; nt < 16; nt++) {
                acc[mt][nt][hf * 2]     *= inv;
                acc[mt][nt][hf * 2 + 1] *= inv;
            }
        }
    __syncthreads();

    float* P = dsm + OFF_P;
    #pragma unroll
    for (int mt = 0; mt < 2; mt++) {
        int lr0 = mbase + mt * 16 + g;
        int lr1 = lr0 + 8;
        #pragma unroll
        for (int nt = 0; nt < 16; nt++) {
            int col = wn * 128 + nt * 8 + 2 * t;
            *reinterpret_cast<float2*>(&P[lr0 * PST + col]) =
                make_float2(acc[mt][nt][0], acc[mt][nt][1]);
            *reinterpret_cast<float2*>(&P[lr1 * PST + col]) =
                make_float2(acc[mt][nt][2], acc[mt][nt][3]);
        }
    }
    __syncthreads();

    float acc2[2][8][4];
    #pragma unroll
    for (int i = 0; i < 2; i++)
        #pragma unroll
        for (int j = 0; j < 8; j++)
            #pragma unroll
            for (int q = 0; q < 4; q++) acc2[i][j][q] = 0.0f;

    {
        float* sV = dsm + OFF_V0;
        #pragma unroll
        for (int i = 0; i < 4; i++) {
            int idx = tid + i * 256, r = idx >> 5, dseg = idx & 31;
            cp16(smem_u32(sV + r * VST + dseg * 4),
                 &Vb[(size_t)r * DIM + dseg * 4]);
        }
        CP_COMMIT();
    }
    for (int c = 0; c < 8; c++) {
        if (c + 1 < 8) {
            float* sV = dsm + (((c + 1) & 1) ? OFF_V1 : OFF_V0);
            #pragma unroll
            for (int i = 0; i < 4; i++) {
                int idx = tid + i * 256, r = idx >> 5, dseg = idx & 31;
                cp16(smem_u32(sV + r * VST + dseg * 4),
                     &Vb[(size_t)((c + 1) * 32 + r) * DIM + dseg * 4]);
            }
            CP_COMMIT();
        } else {
            CP_COMMIT();
        }
        CP_WAIT1();
        __syncthreads();
        const uint32_t* sP = (const uint32_t*)P;
        const uint32_t* sV = (const uint32_t*)(dsm + ((c & 1) ? OFF_V1 : OFF_V0));
        #pragma unroll
        for (int kk = 0; kk < 32; kk += 8) {
            uint32_t af[2][4];
            #pragma unroll
            for (int mt = 0; mt < 2; mt++) {
                int r = mbase + mt * 16 + g;
                af[mt][0] = sP[r * PST + c * 32 + kk + t];
                af[mt][1] = sP[(r + 8) * PST + c * 32 + kk + t];
                af[mt][2] = sP[r * PST + c * 32 + kk + t + 4];
                af[mt][3] = sP[(r + 8) * PST + c * 32 + kk + t + 4];
            }
            uint32_t bf[8][2];
            #pragma unroll
            for (int nt = 0; nt < 8; nt++) {
                int d = nbase2 + nt * 8 + g;
                bf[nt][0] = sV[(kk + t) * VST + d];
                bf[nt][1] = sV[(kk + t + 4) * VST + d];
            }
            #pragma unroll
            for (int mt = 0; mt < 2; mt++)
                #pragma unroll
                for (int nt = 0; nt < 8; nt++)
                    mma_tf32(acc2[mt][nt], af[mt], bf[nt]);
        }
        __syncthreads();
    }

    #pragma unroll
    for (int mt = 0; mt < 2; mt++) {
        #pragma unroll
        for (int nt = 0; nt < 8; nt++) {
            int col = nbase2 + nt * 8 + 2 * t;
            int rr0 = l0 + mbase + mt * 16 + g;
            int rr1 = rr0 + 8;
            float* dst0 = &CTX[(size_t)(b * SEQ + rr0) * DIM + h * DHD + col];
            float* dst1 = &CTX[(size_t)(b * SEQ + rr1) * DIM + h * DHD + col];
            *reinterpret_cast<float2*>(dst0) = make_float2(acc2[mt][nt][0], acc2[mt][nt][1]);
            *reinterpret_cast<float2*>(dst1) = make_float2(acc2[mt][nt][2], acc2[mt][nt][3]);
        }
    }
}

// ---------------- fused weight prep: all transposes + dist pad --------------
__global__ void wprep(const float* __restrict__ Wq, const float* __restrict__ Wk,
                      const float* __restrict__ Wv, const float* __restrict__ Wo,
                      const float* __restrict__ Wi, const float* __restrict__ Wo2,
                      const float* __restrict__ dist,
                      float* __restrict__ WqT, float* __restrict__ WkT,
                      float* __restrict__ WvT, float* __restrict__ WoT,
                      float* __restrict__ WiT, float* __restrict__ Wo2T,
                      float* __restrict__ dPp) {
    int z = blockIdx.z;
    int i = blockIdx.x * 256 + threadIdx.x;
    if (z < 4) {
        const float* S = (z == 0) ? Wq : (z == 1) ? Wk : (z == 2) ? Wv : Wo;
        float* D       = (z == 0) ? WqT : (z == 1) ? WkT : (z == 2) ? WvT : WoT;
        int l = i >> 18;
        int w = i & 262143;
        int k = w >> 9, n = w & 511;
        D[(size_t)l * 262144 + n * 512 + k] = tf32_rna(S[i]);
    } else if (z == 4) {
        if (i < LNUM * DIM * FFI) {
            int l = i >> 16, w = i & 65535;
            int k = w >> 7, n = w & 127;
            WiT[(size_t)l * 65536 + n * 512 + k] = tf32_rna(Wi[i]);
        }
    } else if (z == 5) {
        if (i < LNUM * FFI * DIM) {
            int l = i >> 16, w = i & 65535;
            int k = w >> 9, n = w & 511;
            Wo2T[(size_t)l * 65536 + n * 128 + k] = tf32_rna(Wo2[i]);
        }
    } else {
        if (i < DPAD * DHD) {
            int pp = i >> 7;
            dPp[i] = (pp < 511) ? tf32_rna(dist[i]) : 0.0f;
        }
    }
}

// --------------------------- embedding + LN ---------------------------------
__device__ __forceinline__ void block_reduce2(float& a, float& b) {
    __shared__ float sa[8], sb[8];
    int lane = threadIdx.x & 31, w = threadIdx.x >> 5;
    #pragma unroll
    for (int o = 16; o; o >>= 1) {
        a += __shfl_xor_sync(0xffffffffu, a, o);
        b += __shfl_xor_sync(0xffffffffu, b, o);
    }
    if (lane == 0) { sa[w] = a; sb[w] = b; }
    __syncthreads();
    if (w == 0) {
        a = (lane < 8) ? sa[lane] : 0.0f;
        b = (lane < 8) ? sb[lane] : 0.0f;
        #pragma unroll
        for (int o = 4; o; o >>= 1) {
            a += __shfl_xor_sync(0xffffffffu, a, o);
            b += __shfl_xor_sync(0xffffffffu, b, o);
        }
        if (lane == 0) { sa[0] = a; sb[0] = b; }
    }
    __syncthreads();
    a = sa[0]; b = sb[0];
}

__global__ void embed_ln(const int* __restrict__ ids, const float* __restrict__ inW,
                         const float* __restrict__ inb, const float* __restrict__ tok,
                         const float* __restrict__ g,  const float* __restrict__ bb,
                         float* __restrict__ X) {
    int tt = blockIdx.x, tid = threadIdx.x;
    float f[NFEAT];
    #pragma unroll
    for (int i = 0; i < NFEAT; i++) f[i] = (float)ids[tt * NFEAT + i];
    int d0 = tid, d1 = tid + 256;
    float v0 = inb[d0] + tok[d0];
    float v1 = inb[d1] + tok[d1];
    #pragma unroll
    for (int i = 0; i < NFEAT; i++) {
        v0 += f[i] * inW[i * DIM + d0];
        v1 += f[i] * inW[i * DIM + d1];
    }
    float s = v0 + v1, q = v0 * v0 + v1 * v1;
    block_reduce2(s, q);
    float mu  = s * (1.0f / DIM);
    float var = q * (1.0f / DIM) - mu * mu;
    float r   = rsqrtf(var + 1e-12f);
    size_t base = (size_t)tt * DIM;
    X[base + d0] = (v0 - mu) * r * g[d0] + bb[d0];
    X[base + d1] = (v1 - mu) * r * g[d1] + bb[d1];
}

// warp-per-token pure LayerNorm (input already has residual added)
__global__ __launch_bounds__(256) void ln_w(
    const float* __restrict__ in,
    const float* __restrict__ g, const float* __restrict__ bb,
    float* __restrict__ out) {
    int wid = threadIdx.x >> 5, lane = threadIdx.x & 31;
    int tt = blockIdx.x * 8 + wid;
    size_t base = (size_t)tt * DIM;
    float4 v[4];
    float s = 0.0f, q = 0.0f;
    #pragma unroll
    for (int i = 0; i < 4; i++) {
        int col = i * 128 + lane * 4;
        v[i] = *reinterpret_cast<const float4*>(&in[base + col]);
        s += v[i].x + v[i].y + v[i].z + v[i].w;
        q += v[i].x * v[i].x + v[i].y * v[i].y + v[i].z * v[i].z + v[i].w * v[i].w;
    }
    #pragma unroll
    for (int o = 16; o; o >>= 1) {
        s += __shfl_xor_sync(0xffffffffu, s, o);
        q += __shfl_xor_sync(0xffffffffu, q, o);
    }
    float mu  = s * (1.0f / DIM);
    float var = q * (1.0f / DIM) - mu * mu;
    float r   = rsqrtf(var + 1e-12f);
    #pragma unroll
    for (int i = 0; i < 4; i++) {
        int col = i * 128 + lane * 4;
        float4 g4 = *reinterpret_cast<const float4*>(&g[col]);
        float4 b4 = *reinterpret_cast<const float4*>(&bb[col]);
        float4 o4;
        o4.x = (v[i].x - mu) * r * g4.x + b4.x;
        o4.y = (v[i].y - mu) * r * g4.y + b4.y;
        o4.z = (v[i].z - mu) * r * g4.z + b4.z;
        o4.w = (v[i].w - mu) * r * g4.w + b4.w;
        *reinterpret_cast<float4*>(&out[base + col]) = o4;
    }
}

// ------------------------------ host driver ----------------------------------
extern "C" void kernel_launch(void* const* d_in, const int* in_sizes, int n_in,
                              void* d_out, int out_size) {
    (void)in_sizes; (void)n_in; (void)out_size;
    const int*   ids  = (const int*)  d_in[0];
    const float* mask = (const float*)d_in[1];
    const float* inW  = (const float*)d_in[2];
    const float* inb  = (const float*)d_in[3];
    const float* tok  = (const float*)d_in[4];
    const float* elg  = (const float*)d_in[5];
    const float* elb  = (const float*)d_in[6];
    const float* dist = (const float*)d_in[7];
    const float* Wq   = (const float*)d_in[8];
    const float* bq   = (const float*)d_in[9];
    const float* Wk   = (const float*)d_in[10];
    const float* bk   = (const float*)d_in[11];
    const float* Wv   = (const float*)d_in[12];
    const float* bv   = (const float*)d_in[13];
    const float* Wo   = (const float*)d_in[14];
    const float* bo   = (const float*)d_in[15];
    const float* ln1g = (const float*)d_in[16];
    const float* ln1b = (const float*)d_in[17];
    const float* Wi   = (const float*)d_in[18];
    const float* bi   = (const float*)d_in[19];
    const float* Wo2  = (const float*)d_in[20];
    const float* bo2  = (const float*)d_in[21];
    const float* ln2g = (const float*)d_in[22];
    const float* ln2b = (const float*)d_in[23];
    float* out = (float*)d_out;

    float *X, *Q, *Kb, *V, *CTX, *TMP, *Hb, *QD, *KD, *dP;
    float *WqT, *WkT, *WvT, *WoT, *WiT, *Wo2T;
    cudaGetSymbolAddress((void**)&X,    g_X);
    cudaGetSymbolAddress((void**)&Q,    g_Q);
    cudaGetSymbolAddress((void**)&Kb,   g_K);
    cudaGetSymbolAddress((void**)&V,    g_V);
    cudaGetSymbolAddress((void**)&CTX,  g_CTX);
    cudaGetSymbolAddress((void**)&TMP,  g_TMP);
    cudaGetSymbolAddress((void**)&Hb,   g_Hb);
    cudaGetSymbolAddress((void**)&QD,   g_QD);
    cudaGetSymbolAddress((void**)&KD,   g_KD);
    cudaGetSymbolAddress((void**)&dP,   g_dP);
    cudaGetSymbolAddress((void**)&WqT,  g_WqT);
    cudaGetSymbolAddress((void**)&WkT,  g_WkT);
    cudaGetSymbolAddress((void**)&WvT,  g_WvT);
    cudaGetSymbolAddress((void**)&WoT,  g_WoT);
    cudaGetSymbolAddress((void**)&WiT,  g_WiT);
    cudaGetSymbolAddress((void**)&Wo2T, g_Wo2T);

    const int GEMM_SMEM  = 2 * STAGEF * 4;
    const int FUSED_SMEM = FUSED_SMEMF * 4;
    cudaFuncSetAttribute(gemm_pipe<0,0,0>, cudaFuncAttributeMaxDynamicSharedMemorySize, GEMM_SMEM);
    cudaFuncSetAttribute(gemm_pipe<0,1,0>, cudaFuncAttributeMaxDynamicSharedMemorySize, GEMM_SMEM);
    cudaFuncSetAttribute(gemm_pipe<0,2,0>, cudaFuncAttributeMaxDynamicSharedMemorySize, GEMM_SMEM);
    cudaFuncSetAttribute(gemm_pipe<0,0,1>, cudaFuncAttributeMaxDynamicSharedMemorySize, GEMM_SMEM);
    cudaFuncSetAttribute(gemm_pipe<1,0,0>, cudaFuncAttributeMaxDynamicSharedMemorySize, GEMM_SMEM);
    cudaFuncSetAttribute(fused_attn,       cudaFuncAttributeMaxDynamicSharedMemorySize, FUSED_SMEM);

    wprep<<<dim3(4096, 1, 7), 256>>>(Wq, Wk, Wv, Wo, Wi, Wo2, dist,
                                     WqT, WkT, WvT, WoT, WiT, Wo2T, dP);
    embed_ln<<<TOK, 256>>>(ids, inW, inb, tok, elg, elb, X);

    dim3 gG(DIM / 128, TOK / 128);
    dim3 gGi(FFI / 128, TOK / 128);
    dim3 gQD(QCOLS / 128, ROWSBH / 128);
    dim3 gA(SEQ / 128, BATCH * NHEAD);

    for (int l = 0; l < LNUM; l++) {
        const float* wqt  = WqT  + (size_t)l * DIM * DIM;
        const float* wkt  = WkT  + (size_t)l * DIM * DIM;
        const float* wvt  = WvT  + (size_t)l * DIM * DIM;
        const float* wot  = WoT  + (size_t)l * DIM * DIM;
        const float* wit  = WiT  + (size_t)l * FFI * DIM;
        const float* wo2t = Wo2T + (size_t)l * DIM * FFI;

        gemm_pipe<0,0,0><<<gG, 256, GEMM_SMEM>>>(X, wqt, bq + l * DIM, nullptr, Q,  DIM, DIM);
        gemm_pipe<0,0,0><<<gG, 256, GEMM_SMEM>>>(X, wkt, bk + l * DIM, nullptr, Kb, DIM, DIM);
        gemm_pipe<0,0,0><<<gG, 256, GEMM_SMEM>>>(X, wvt, bv + l * DIM, nullptr, V,  DIM, DIM);

        gemm_pipe<0,1,0><<<gQD, 256, GEMM_SMEM>>>(Q,  dP, nullptr, nullptr, QD, DHD, QCOLS);
        gemm_pipe<0,2,0><<<gQD, 256, GEMM_SMEM>>>(Kb, dP, nullptr, nullptr, KD, DHD, QCOLS);

        fused_attn<<<gA, 256, FUSED_SMEM>>>(Q, Kb, V, QD, KD, mask, CTX);

        gemm_pipe<0,0,1><<<gG, 256, GEMM_SMEM>>>(CTX, wot, bo + l * DIM, X, TMP, DIM, DIM);
        ln_w<<<TOK / 8, 256>>>(TMP, ln1g + l * DIM, ln1b + l * DIM, X);

        gemm_pipe<1,0,0><<<gGi, 256, GEMM_SMEM>>>(X, wit, bi + l * FFI, nullptr, Hb, DIM, FFI);
        gemm_pipe<0,0,1><<<gG, 256, GEMM_SMEM>>>(Hb, wo2t, bo2 + l * DIM, X, TMP, FFI, DIM);
        ln_w<<<TOK / 8, 256>>>(TMP, ln2g + l * DIM, ln2b + l * DIM,
                               (l == LNUM - 1) ? out : X);
    }
}

// round 11
// speedup vs baseline: 1.2023x; 1.0199x over previous
#include <cuda_runtime.h>
#include <math.h>
#include <stdint.h>

// ---------------------------------------------------------------------------
// ExpressionBert forward. tf32 mma.sync + cp.async pipelines.
// Round 11: canonical 3-stage cp.async ring in gemm_pipe with ONE
// __syncthreads per K-chunk (wait -> sync -> prefetch c+2 -> compute c).
// Keeps round-10's launch_bounds(256,2), wprep fusion, residual epilogues.
// ---------------------------------------------------------------------------

#define LNUM   4
#define DIM    512
#define NHEAD  4
#define DHD    128
#define FFI    128
#define SEQ    256
#define BATCH  128
#define NFEAT  6
#define TOK    (BATCH*SEQ)          // 32768
#define ROWSBH (BATCH*NHEAD*SEQ)    // 131072
#define QCOLS  384
#define DPAD   608

#define SM_SCALE 0.08838834764831845f  // 1/sqrt(128)

// ------------------------- static device scratch ---------------------------
__device__ float g_X  [TOK*DIM];
__device__ float g_Q  [TOK*DIM];
__device__ float g_K  [TOK*DIM];
__device__ float g_V  [TOK*DIM];
__device__ float g_CTX[TOK*DIM];
__device__ float g_TMP[TOK*DIM];
__device__ float g_Hb [TOK*FFI];
__device__ float g_QD [(size_t)ROWSBH*QCOLS];
__device__ float g_KD [(size_t)ROWSBH*QCOLS];
__device__ float g_dP [DPAD*DHD];

__device__ float g_WqT [LNUM*DIM*DIM];
__device__ float g_WkT [LNUM*DIM*DIM];
__device__ float g_WvT [LNUM*DIM*DIM];
__device__ float g_WoT [LNUM*DIM*DIM];
__device__ float g_WiT [LNUM*FFI*DIM];
__device__ float g_Wo2T[LNUM*DIM*FFI];

// ------------------------------ helpers -------------------------------------
__device__ __forceinline__ uint32_t smem_u32(const void* p) {
    uint32_t a;
    asm("{ .reg .u64 t; cvta.to.shared.u64 t, %1; cvt.u32.u64 %0, t; }"
        : "=r"(a) : "l"(p));
    return a;
}

__device__ __forceinline__ float gelu_exact(float x) {
    return 0.5f * x * (1.0f + erff(x * 0.70710678118654752440f));
}

__device__ __forceinline__ float tf32_rna(float f) {
    uint32_t u;
    asm("cvt.rna.tf32.f32 %0, %1;" : "=r"(u) : "f"(f));
    return __uint_as_float(u);
}

__device__ __forceinline__ void mma_tf32(float* d, const uint32_t* a,
                                         const uint32_t* b) {
    asm volatile(
        "mma.sync.aligned.m16n8k8.row.col.f32.tf32.tf32.f32 "
        "{%0,%1,%2,%3}, {%4,%5,%6,%7}, {%8,%9}, {%0,%1,%2,%3};"
        : "+f"(d[0]), "+f"(d[1]), "+f"(d[2]), "+f"(d[3])
        : "r"(a[0]), "r"(a[1]), "r"(a[2]), "r"(a[3]), "r"(b[0]), "r"(b[1]));
}

__device__ __forceinline__ void cp16(uint32_t saddr, const void* gptr) {
    asm volatile("cp.async.cg.shared.global [%0], [%1], 16;"
                 :: "r"(saddr), "l"(gptr) : "memory");
}
#define CP_COMMIT() asm volatile("cp.async.commit_group;" ::: "memory")
#define CP_WAIT1()  asm volatile("cp.async.wait_group 1;" ::: "memory")

#define SST 36
#define STAGEF 9216
#define NSTAGE 3

#define FRAG_COMPUTE(sA, sB)                                                   \
    _Pragma("unroll")                                                          \
    for (int kk = 0; kk < 32; kk += 8) {                                       \
        uint32_t af[2][4];                                                     \
        _Pragma("unroll")                                                      \
        for (int mt = 0; mt < 2; mt++) {                                       \
            int r = mbase + mt * 16 + g;                                       \
            af[mt][0] = (sA)[r * SST + kk + t];                                \
            af[mt][1] = (sA)[(r + 8) * SST + kk + t];                          \
            af[mt][2] = (sA)[r * SST + kk + t + 4];                            \
            af[mt][3] = (sA)[(r + 8) * SST + kk + t + 4];                      \
        }                                                                      \
        uint32_t bf[8][2];                                                     \
        _Pragma("unroll")                                                      \
        for (int nt = 0; nt < 8; nt++) {                                       \
            int r = nbase + nt * 8 + g;                                        \
            bf[nt][0] = (sB)[r * SST + kk + t];                                \
            bf[nt][1] = (sB)[r * SST + kk + t + 4];                            \
        }                                                                      \
        _Pragma("unroll")                                                      \
        for (int mt = 0; mt < 2; mt++)                                         \
            _Pragma("unroll")                                                  \
            for (int nt = 0; nt < 8; nt++)                                     \
                mma_tf32(acc[mt][nt], af[mt], bf[nt]);                         \
    }

// -------------- pipelined tf32 GEMM, 3-stage ring, 1 sync/chunk -------------
// C = A @ Beff^T + bias (+GELU) (+R residual). MODE 0 plain, 1 QD, 2 KD.
template<int GELU, int MODE, int RESID>
__global__ __launch_bounds__(256, 2) void gemm_pipe(
    const float* __restrict__ A, const float* __restrict__ BT,
    const float* __restrict__ bias, const float* __restrict__ R,
    float* __restrict__ C, int K, int N) {
    extern __shared__ float dsm[];
    int tid  = threadIdx.x;
    int wid  = tid >> 5, lane = tid & 31;
    int g    = lane >> 2, t = lane & 3;
    int m0   = blockIdx.y * 128;
    int n0   = blockIdx.x * 128;
    int wm   = wid >> 1, wn = wid & 1;
    int mbase = wm * 32, nbase = wn * 64;

    const float* Beff = BT;
    if (MODE == 1) Beff = BT + (size_t)((m0 & 1023) >> 2) * K;
    if (MODE == 2) Beff = BT + (size_t)(224 - ((m0 & 1023) >> 2)) * K;

    float acc[2][8][4];
    #pragma unroll
    for (int i = 0; i < 2; i++)
        #pragma unroll
        for (int j = 0; j < 8; j++)
            #pragma unroll
            for (int q = 0; q < 4; q++) acc[i][j][q] = 0.0f;

    int nch = K >> 5;

    // per-thread staging coordinates (constant across chunks)
    int srow = tid >> 3;                  // 0..31 handled x4 below via +32*i? no:
    // we use the same 4x loop as before; precompute row/seg pairs
    // (kept identical addressing to verified kernel)

    // prologue: prefetch chunk 0 and 1
    #pragma unroll
    for (int s = 0; s < 2; s++) {
        float* sA = dsm + s * STAGEF;
        float* sB = sA + 4608;
        #pragma unroll
        for (int i = 0; i < 4; i++) {
            int idx = tid + i * 256, row = idx >> 3, seg = idx & 7;
            cp16(smem_u32(sA + row * SST + seg * 4),
                 &A[(size_t)(m0 + row) * K + s * 32 + seg * 4]);
            cp16(smem_u32(sB + row * SST + seg * 4),
                 &Beff[(size_t)(n0 + row) * K + s * 32 + seg * 4]);
        }
        CP_COMMIT();
    }
    (void)srow;

    int stage = 0;
    for (int c = 0; c < nch; c++) {
        CP_WAIT1();              // stage c complete (c+1 may be in flight)
        __syncthreads();         // all warps' iter c-1 compute done + data visible
        if (c + 2 < nch) {       // prefetch chunk c+2 into ring slot
            int s = (stage + 2) % NSTAGE;
            float* sA = dsm + s * STAGEF;
            float* sB = sA + 4608;
            #pragma unroll
            for (int i = 0; i < 4; i++) {
                int idx = tid + i * 256, row = idx >> 3, seg = idx & 7;
                cp16(smem_u32(sA + row * SST + seg * 4),
                     &A[(size_t)(m0 + row) * K + (c + 2) * 32 + seg * 4]);
                cp16(smem_u32(sB + row * SST + seg * 4),
                     &Beff[(size_t)(n0 + row) * K + (c + 2) * 32 + seg * 4]);
            }
        }
        CP_COMMIT();             // always commit (possibly empty group)
        const uint32_t* sA = (const uint32_t*)(dsm + stage * STAGEF);
        const uint32_t* sB = sA + 4608;
        FRAG_COMPUTE(sA, sB);
        stage = (stage + 1) % NSTAGE;
    }

    #pragma unroll
    for (int mt = 0; mt < 2; mt++) {
        #pragma unroll
        for (int nt = 0; nt < 8; nt++) {
            int col = n0 + nbase + nt * 8 + 2 * t;
            float b0 = bias ? bias[col]     : 0.0f;
            float b1 = bias ? bias[col + 1] : 0.0f;
            int r0 = m0 + mbase + mt * 16 + g;
            int r1 = r0 + 8;
            float v00 = acc[mt][nt][0] + b0, v01 = acc[mt][nt][1] + b1;
            float v10 = acc[mt][nt][2] + b0, v11 = acc[mt][nt][3] + b1;
            if (GELU) {
                v00 = gelu_exact(v00); v01 = gelu_exact(v01);
                v10 = gelu_exact(v10); v11 = gelu_exact(v11);
            }
            if (RESID) {
                float2 x0 = *reinterpret_cast<const float2*>(&R[(size_t)r0 * N + col]);
                float2 x1 = *reinterpret_cast<const float2*>(&R[(size_t)r1 * N + col]);
                v00 += x0.x; v01 += x0.y;
                v10 += x1.x; v11 += x1.y;
            }
            *reinterpret_cast<float2*>(&C[(size_t)r0 * N + col]) = make_float2(v00, v01);
            *reinterpret_cast<float2*>(&C[(size_t)r1 * N + col]) = make_float2(v10, v11);
        }
    }
}

// ------------- fused attention: scores + softmax + ctx (verified r8) --------
#define PST 260
#define VST 132
#define OFF_Q0  0
#define OFF_Q1  4608
#define OFF_K0  9216
#define OFF_K1  18432
#define OFF_P   0
#define OFF_V0  33280
#define OFF_V1  37504
#define OFF_RED 41728
#define FUSED_SMEMF 42240

__global__ __launch_bounds__(256) void fused_attn(
    const float* __restrict__ Q, const float* __restrict__ Km,
    const float* __restrict__ V,
    const float* __restrict__ QD, const float* __restrict__ KD,
    const float* __restrict__ mask, float* __restrict__ CTX) {
    extern __shared__ float dsm[];
    int tid  = threadIdx.x;
    int wid  = tid >> 5, lane = tid & 31;
    int g    = lane >> 2, t = lane & 3;
    int l0   = blockIdx.x * 128;
    int bh   = blockIdx.y;
    int b    = bh >> 2, h = bh & 3;
    int wm   = wid >> 1, wn = wid & 1;
    int mbase = wm * 32;
    int nbase2 = wn * 64;

    const float* Qb = Q  + (size_t)b * SEQ * DIM + h * DHD;
    const float* Kb = Km + (size_t)b * SEQ * DIM + h * DHD;
    const float* Vb = V  + (size_t)b * SEQ * DIM + h * DHD;

    float acc[2][16][4];
    #pragma unroll
    for (int i = 0; i < 2; i++)
        #pragma unroll
        for (int j = 0; j < 16; j++)
            #pragma unroll
            for (int q = 0; q < 4; q++) acc[i][j][q] = 0.0f;

    {
        float* sQ = dsm + OFF_Q0;
        float* sK = dsm + OFF_K0;
        #pragma unroll
        for (int i = 0; i < 4; i++) {
            int idx = tid + i * 256, row = idx >> 3, seg = idx & 7;
            cp16(smem_u32(sQ + row * SST + seg * 4),
                 &Qb[(size_t)(l0 + row) * DIM + seg * 4]);
        }
        #pragma unroll
        for (int i = 0; i < 8; i++) {
            int idx = tid + i * 256, row = idx >> 3, seg = idx & 7;
            cp16(smem_u32(sK + row * SST + seg * 4),
                 &Kb[(size_t)row * DIM + seg * 4]);
        }
        CP_COMMIT();
    }
    for (int c = 0; c < 4; c++) {
        if (c + 1 < 4) {
            float* sQ = dsm + ((c + 1) & 1 ? OFF_Q1 : OFF_Q0);
            float* sK = dsm + ((c + 1) & 1 ? OFF_K1 : OFF_K0);
            #pragma unroll
            for (int i = 0; i < 4; i++) {
                int idx = tid + i * 256, row = idx >> 3, seg = idx & 7;
                cp16(smem_u32(sQ + row * SST + seg * 4),
                     &Qb[(size_t)(l0 + row) * DIM + (c + 1) * 32 + seg * 4]);
            }
            #pragma unroll
            for (int i = 0; i < 8; i++) {
                int idx = tid + i * 256, row = idx >> 3, seg = idx & 7;
                cp16(smem_u32(sK + row * SST + seg * 4),
                     &Kb[(size_t)row * DIM + (c + 1) * 32 + seg * 4]);
            }
            CP_COMMIT();
        } else {
            CP_COMMIT();
        }
        CP_WAIT1();
        __syncthreads();
        const uint32_t* sQ = (const uint32_t*)(dsm + ((c & 1) ? OFF_Q1 : OFF_Q0));
        const uint32_t* sK = (const uint32_t*)(dsm + ((c & 1) ? OFF_K1 : OFF_K0));
        #pragma unroll
        for (int kk = 0; kk < 32; kk += 8) {
            uint32_t af[2][4];
            #pragma unroll
            for (int mt = 0; mt < 2; mt++) {
                int r = mbase + mt * 16 + g;
                af[mt][0] = sQ[r * SST + kk + t];
                af[mt][1] = sQ[(r + 8) * SST + kk + t];
                af[mt][2] = sQ[r * SST + kk + t + 4];
                af[mt][3] = sQ[(r + 8) * SST + kk + t + 4];
            }
            #pragma unroll
            for (int nth = 0; nth < 2; nth++) {
                uint32_t bf[8][2];
                #pragma unroll
                for (int j = 0; j < 8; j++) {
                    int r = wn * 128 + nth * 64 + j * 8 + g;
                    bf[j][0] = sK[r * SST + kk + t];
                    bf[j][1] = sK[r * SST + kk + t + 4];
                }
                #pragma unroll
                for (int mt = 0; mt < 2; mt++)
                    #pragma unroll
                    for (int j = 0; j < 8; j++)
                        mma_tf32(acc[mt][nth * 8 + j], af[mt], bf[j]);
            }
        }
        __syncthreads();
    }

    #pragma unroll
    for (int mt = 0; mt < 2; mt++) {
        int ll0 = l0 + mbase + mt * 16 + g;
        int ll1 = ll0 + 8;
        size_t qdr0 = ((size_t)(b * SEQ + ll0) * NHEAD + h) * QCOLS;
        size_t qdr1 = ((size_t)(b * SEQ + ll1) * NHEAD + h) * QCOLS;
        #pragma unroll
        for (int nt = 0; nt < 16; nt++) {
            int rr0 = wn * 128 + nt * 8 + 2 * t;
            int rr1 = rr0 + 1;
            size_t kdr0 = ((size_t)(b * SEQ + rr0) * NHEAD + h) * QCOLS;
            size_t kdr1 = ((size_t)(b * SEQ + rr1) * NHEAD + h) * QCOLS;
            float bias0 = (1.0f - mask[b * SEQ + rr0]) * (-1e9f);
            float bias1 = (1.0f - mask[b * SEQ + rr1]) * (-1e9f);
            int jq00 = (ll0 & 31) + 255 - rr0, jq01 = jq00 - 1;
            int jq10 = (ll1 & 31) + 255 - rr0, jq11 = jq10 - 1;
            int jk00 = ll0 - (rr0 & 31) + 31,  jk01 = ll0 - (rr1 & 31) + 31;
            int jk10 = ll1 - (rr0 & 31) + 31,  jk11 = ll1 - (rr1 & 31) + 31;
            acc[mt][nt][0] = (acc[mt][nt][0] + QD[qdr0 + jq00] + KD[kdr0 + jk00]) * SM_SCALE + bias0;
            acc[mt][nt][1] = (acc[mt][nt][1] + QD[qdr0 + jq01] + KD[kdr1 + jk01]) * SM_SCALE + bias1;
            acc[mt][nt][2] = (acc[mt][nt][2] + QD[qdr1 + jq10] + KD[kdr0 + jk10]) * SM_SCALE + bias0;
            acc[mt][nt][3] = (acc[mt][nt][3] + QD[qdr1 + jq11] + KD[kdr1 + jk11]) * SM_SCALE + bias1;
        }
    }

    float* rmax = dsm + OFF_RED;
    float* rsum = dsm + OFF_RED + 256;
    float mx[2][2];
    #pragma unroll
    for (int mt = 0; mt < 2; mt++)
        #pragma unroll
        for (int hf = 0; hf < 2; hf++) {
            float m = -1e30f;
            #pragma unroll
            for (int nt = 0; nt < 16; nt++) {
                m = fmaxf(m, acc[mt][nt][hf * 2]);
                m = fmaxf(m, acc[mt][nt][hf * 2 + 1]);
            }
            m = fmaxf(m, __shfl_xor_sync(0xffffffffu, m, 1));
            m = fmaxf(m, __shfl_xor_sync(0xffffffffu, m, 2));
            mx[mt][hf] = m;
        }
    if (t == 0) {
        #pragma unroll
        for (int mt = 0; mt < 2; mt++)
            #pragma unroll
            for (int hf = 0; hf < 2; hf++) {
                int lrow = mbase + mt * 16 + hf * 8 + g;
                rmax[wn * 128 + lrow] = mx[mt][hf];
            }
    }
    __syncthreads();
    #pragma unroll
    for (int mt = 0; mt < 2; mt++)
        #pragma unroll
        for (int hf = 0; hf < 2; hf++) {
            int lrow = mbase + mt * 16 + hf * 8 + g;
            float m = fmaxf(rmax[lrow], rmax[128 + lrow]);
            float s = 0.0f;
            #pragma unroll
            for (int nt = 0; nt < 16; nt++) {
                float e0 = __expf(acc[mt][nt][hf * 2]     - m);
                float e1 = __expf(acc[mt][nt][hf * 2 + 1] - m);
                acc[mt][nt][hf * 2]     = e0;
                acc[mt][nt][hf * 2 + 1] = e1;
                s += e0 + e1;
            }
            s += __shfl_xor_sync(0xffffffffu, s, 1);
            s += __shfl_xor_sync(0xffffffffu, s, 2);
            if (t == 0) rsum[wn * 128 + lrow] = s;
        }
    __syncthreads();
    #pragma unroll
    for (int mt = 0; mt < 2; mt++)
        #pragma unroll
        for (int hf = 0; hf < 2; hf++) {
            int lrow = mbase + mt * 16 + hf * 8 + g;
            float inv = 1.0f / (rsum[lrow] + rsum[128 + lrow]);
            #pragma unroll
            for (int nt = 0; nt < 16; nt++) {
                acc[mt][nt][hf * 2]     *= inv;
                acc[mt][nt][hf * 2 + 1] *= inv;
            }
        }
    __syncthreads();

    float* P = dsm + OFF_P;
    #pragma unroll
    for (int mt = 0; mt < 2; mt++) {
        int lr0 = mbase + mt * 16 + g;
        int lr1 = lr0 + 8;
        #pragma unroll
        for (int nt = 0; nt < 16; nt++) {
            int col = wn * 128 + nt * 8 + 2 * t;
            *reinterpret_cast<float2*>(&P[lr0 * PST + col]) =
                make_float2(acc[mt][nt][0], acc[mt][nt][1]);
            *reinterpret_cast<float2*>(&P[lr1 * PST + col]) =
                make_float2(acc[mt][nt][2], acc[mt][nt][3]);
        }
    }
    __syncthreads();

    float acc2[2][8][4];
    #pragma unroll
    for (int i = 0; i < 2; i++)
        #pragma unroll
        for (int j = 0; j < 8; j++)
            #pragma unroll
            for (int q = 0; q < 4; q++) acc2[i][j][q] = 0.0f;

    {
        float* sV = dsm + OFF_V0;
        #pragma unroll
        for (int i = 0; i < 4; i++) {
            int idx = tid + i * 256, r = idx >> 5, dseg = idx & 31;
            cp16(smem_u32(sV + r * VST + dseg * 4),
                 &Vb[(size_t)r * DIM + dseg * 4]);
        }
        CP_COMMIT();
    }
    for (int c = 0; c < 8; c++) {
        if (c + 1 < 8) {
            float* sV = dsm + (((c + 1) & 1) ? OFF_V1 : OFF_V0);
            #pragma unroll
            for (int i = 0; i < 4; i++) {
                int idx = tid + i * 256, r = idx >> 5, dseg = idx & 31;
                cp16(smem_u32(sV + r * VST + dseg * 4),
                     &Vb[(size_t)((c + 1) * 32 + r) * DIM + dseg * 4]);
            }
            CP_COMMIT();
        } else {
            CP_COMMIT();
        }
        CP_WAIT1();
        __syncthreads();
        const uint32_t* sP = (const uint32_t*)P;
        const uint32_t* sV = (const uint32_t*)(dsm + ((c & 1) ? OFF_V1 : OFF_V0));
        #pragma unroll
        for (int kk = 0; kk < 32; kk += 8) {
            uint32_t af[2][4];
            #pragma unroll
            for (int mt = 0; mt < 2; mt++) {
                int r = mbase + mt * 16 + g;
                af[mt][0] = sP[r * PST + c * 32 + kk + t];
                af[mt][1] = sP[(r + 8) * PST + c * 32 + kk + t];
                af[mt][2] = sP[r * PST + c * 32 + kk + t + 4];
                af[mt][3] = sP[(r + 8) * PST + c * 32 + kk + t + 4];
            }
            uint32_t bf[8][2];
            #pragma unroll
            for (int nt = 0; nt < 8; nt++) {
                int d = nbase2 + nt * 8 + g;
                bf[nt][0] = sV[(kk + t) * VST + d];
                bf[nt][1] = sV[(kk + t + 4) * VST + d];
            }
            #pragma unroll
            for (int mt = 0; mt < 2; mt++)
                #pragma unroll
                for (int nt = 0; nt < 8; nt++)
                    mma_tf32(acc2[mt][nt], af[mt], bf[nt]);
        }
        __syncthreads();
    }

    #pragma unroll
    for (int mt = 0; mt < 2; mt++) {
        #pragma unroll
        for (int nt = 0; nt < 8; nt++) {
            int col = nbase2 + nt * 8 + 2 * t;
            int rr0 = l0 + mbase + mt * 16 + g;
            int rr1 = rr0 + 8;
            float* dst0 = &CTX[(size_t)(b * SEQ + rr0) * DIM + h * DHD + col];
            float* dst1 = &CTX[(size_t)(b * SEQ + rr1) * DIM + h * DHD + col];
            *reinterpret_cast<float2*>(dst0) = make_float2(acc2[mt][nt][0], acc2[mt][nt][1]);
            *reinterpret_cast<float2*>(dst1) = make_float2(acc2[mt][nt][2], acc2[mt][nt][3]);
        }
    }
}

// ---------------- fused weight prep: all transposes + dist pad --------------
__global__ void wprep(const float* __restrict__ Wq, const float* __restrict__ Wk,
                      const float* __restrict__ Wv, const float* __restrict__ Wo,
                      const float* __restrict__ Wi, const float* __restrict__ Wo2,
                      const float* __restrict__ dist,
                      float* __restrict__ WqT, float* __restrict__ WkT,
                      float* __restrict__ WvT, float* __restrict__ WoT,
                      float* __restrict__ WiT, float* __restrict__ Wo2T,
                      float* __restrict__ dPp) {
    int z = blockIdx.z;
    int i = blockIdx.x * 256 + threadIdx.x;
    if (z < 4) {
        const float* S = (z == 0) ? Wq : (z == 1) ? Wk : (z == 2) ? Wv : Wo;
        float* D       = (z == 0) ? WqT : (z == 1) ? WkT : (z == 2) ? WvT : WoT;
        int l = i >> 18;
        int w = i & 262143;
        int k = w >> 9, n = w & 511;
        D[(size_t)l * 262144 + n * 512 + k] = tf32_rna(S[i]);
    } else if (z == 4) {
        if (i < LNUM * DIM * FFI) {
            int l = i >> 16, w = i & 65535;
            int k = w >> 7, n = w & 127;
            WiT[(size_t)l * 65536 + n * 512 + k] = tf32_rna(Wi[i]);
        }
    } else if (z == 5) {
        if (i < LNUM * FFI * DIM) {
            int l = i >> 16, w = i & 65535;
            int k = w >> 9, n = w & 511;
            Wo2T[(size_t)l * 65536 + n * 128 + k] = tf32_rna(Wo2[i]);
        }
    } else {
        if (i < DPAD * DHD) {
            int pp = i >> 7;
            dPp[i] = (pp < 511) ? tf32_rna(dist[i]) : 0.0f;
        }
    }
}

// --------------------------- embedding + LN ---------------------------------
__device__ __forceinline__ void block_reduce2(float& a, float& b) {
    __shared__ float sa[8], sb[8];
    int lane = threadIdx.x & 31, w = threadIdx.x >> 5;
    #pragma unroll
    for (int o = 16; o; o >>= 1) {
        a += __shfl_xor_sync(0xffffffffu, a, o);
        b += __shfl_xor_sync(0xffffffffu, b, o);
    }
    if (lane == 0) { sa[w] = a; sb[w] = b; }
    __syncthreads();
    if (w == 0) {
        a = (lane < 8) ? sa[lane] : 0.0f;
        b = (lane < 8) ? sb[lane] : 0.0f;
        #pragma unroll
        for (int o = 4; o; o >>= 1) {
            a += __shfl_xor_sync(0xffffffffu, a, o);
            b += __shfl_xor_sync(0xffffffffu, b, o);
        }
        if (lane == 0) { sa[0] = a; sb[0] = b; }
    }
    __syncthreads();
    a = sa[0]; b = sb[0];
}

__global__ void embed_ln(const int* __restrict__ ids, const float* __restrict__ inW,
                         const float* __restrict__ inb, const float* __restrict__ tok,
                         const float* __restrict__ g,  const float* __restrict__ bb,
                         float* __restrict__ X) {
    int tt = blockIdx.x, tid = threadIdx.x;
    float f[NFEAT];
    #pragma unroll
    for (int i = 0; i < NFEAT; i++) f[i] = (float)ids[tt * NFEAT + i];
    int d0 = tid, d1 = tid + 256;
    float v0 = inb[d0] + tok[d0];
    float v1 = inb[d1] + tok[d1];
    #pragma unroll
    for (int i = 0; i < NFEAT; i++) {
        v0 += f[i] * inW[i * DIM + d0];
        v1 += f[i] * inW[i * DIM + d1];
    }
    float s = v0 + v1, q = v0 * v0 + v1 * v1;
    block_reduce2(s, q);
    float mu  = s * (1.0f / DIM);
    float var = q * (1.0f / DIM) - mu * mu;
    float r   = rsqrtf(var + 1e-12f);
    size_t base = (size_t)tt * DIM;
    X[base + d0] = (v0 - mu) * r * g[d0] + bb[d0];
    X[base + d1] = (v1 - mu) * r * g[d1] + bb[d1];
}

// warp-per-token pure LayerNorm
__global__ __launch_bounds__(256) void ln_w(
    const float* __restrict__ in,
    const float* __restrict__ g, const float* __restrict__ bb,
    float* __restrict__ out) {
    int wid = threadIdx.x >> 5, lane = threadIdx.x & 31;
    int tt = blockIdx.x * 8 + wid;
    size_t base = (size_t)tt * DIM;
    float4 v[4];
    float s = 0.0f, q = 0.0f;
    #pragma unroll
    for (int i = 0; i < 4; i++) {
        int col = i * 128 + lane * 4;
        v[i] = *reinterpret_cast<const float4*>(&in[base + col]);
        s += v[i].x + v[i].y + v[i].z + v[i].w;
        q += v[i].x * v[i].x + v[i].y * v[i].y + v[i].z * v[i].z + v[i].w * v[i].w;
    }
    #pragma unroll
    for (int o = 16; o; o >>= 1) {
        s += __shfl_xor_sync(0xffffffffu, s, o);
        q += __shfl_xor_sync(0xffffffffu, q, o);
    }
    float mu  = s * (1.0f / DIM);
    float var = q * (1.0f / DIM) - mu * mu;
    float r   = rsqrtf(var + 1e-12f);
    #pragma unroll
    for (int i = 0; i < 4; i++) {
        int col = i * 128 + lane * 4;
        float4 g4 = *reinterpret_cast<const float4*>(&g[col]);
        float4 b4 = *reinterpret_cast<const float4*>(&bb[col]);
        float4 o4;
        o4.x = (v[i].x - mu) * r * g4.x + b4.x;
        o4.y = (v[i].y - mu) * r * g4.y + b4.y;
        o4.z = (v[i].z - mu) * r * g4.z + b4.z;
        o4.w = (v[i].w - mu) * r * g4.w + b4.w;
        *reinterpret_cast<float4*>(&out[base + col]) = o4;
    }
}

// ------------------------------ host driver ----------------------------------
extern "C" void kernel_launch(void* const* d_in, const int* in_sizes, int n_in,
                              void* d_out, int out_size) {
    (void)in_sizes; (void)n_in; (void)out_size;
    const int*   ids  = (const int*)  d_in[0];
    const float* mask = (const float*)d_in[1];
    const float* inW  = (const float*)d_in[2];
    const float* inb  = (const float*)d_in[3];
    const float* tok  = (const float*)d_in[4];
    const float* elg  = (const float*)d_in[5];
    const float* elb  = (const float*)d_in[6];
    const float* dist = (const float*)d_in[7];
    const float* Wq   = (const float*)d_in[8];
    const float* bq   = (const float*)d_in[9];
    const float* Wk   = (const float*)d_in[10];
    const float* bk   = (const float*)d_in[11];
    const float* Wv   = (const float*)d_in[12];
    const float* bv   = (const float*)d_in[13];
    const float* Wo   = (const float*)d_in[14];
    const float* bo   = (const float*)d_in[15];
    const float* ln1g = (const float*)d_in[16];
    const float* ln1b = (const float*)d_in[17];
    const float* Wi   = (const float*)d_in[18];
    const float* bi   = (const float*)d_in[19];
    const float* Wo2  = (const float*)d_in[20];
    const float* bo2  = (const float*)d_in[21];
    const float* ln2g = (const float*)d_in[22];
    const float* ln2b = (const float*)d_in[23];
    float* out = (float*)d_out;

    float *X, *Q, *Kb, *V, *CTX, *TMP, *Hb, *QD, *KD, *dP;
    float *WqT, *WkT, *WvT, *WoT, *WiT, *Wo2T;
    cudaGetSymbolAddress((void**)&X,    g_X);
    cudaGetSymbolAddress((void**)&Q,    g_Q);
    cudaGetSymbolAddress((void**)&Kb,   g_K);
    cudaGetSymbolAddress((void**)&V,    g_V);
    cudaGetSymbolAddress((void**)&CTX,  g_CTX);
    cudaGetSymbolAddress((void**)&TMP,  g_TMP);
    cudaGetSymbolAddress((void**)&Hb,   g_Hb);
    cudaGetSymbolAddress((void**)&QD,   g_QD);
    cudaGetSymbolAddress((void**)&KD,   g_KD);
    cudaGetSymbolAddress((void**)&dP,   g_dP);
    cudaGetSymbolAddress((void**)&WqT,  g_WqT);
    cudaGetSymbolAddress((void**)&WkT,  g_WkT);
    cudaGetSymbolAddress((void**)&WvT,  g_WvT);
    cudaGetSymbolAddress((void**)&WoT,  g_WoT);
    cudaGetSymbolAddress((void**)&WiT,  g_WiT);
    cudaGetSymbolAddress((void**)&Wo2T, g_Wo2T);

    const int GEMM_SMEM  = NSTAGE * STAGEF * 4;     // 110592
    const int FUSED_SMEM = FUSED_SMEMF * 4;
    cudaFuncSetAttribute(gemm_pipe<0,0,0>, cudaFuncAttributeMaxDynamicSharedMemorySize, GEMM_SMEM);
    cudaFuncSetAttribute(gemm_pipe<0,1,0>, cudaFuncAttributeMaxDynamicSharedMemorySize, GEMM_SMEM);
    cudaFuncSetAttribute(gemm_pipe<0,2,0>, cudaFuncAttributeMaxDynamicSharedMemorySize, GEMM_SMEM);
    cudaFuncSetAttribute(gemm_pipe<0,0,1>, cudaFuncAttributeMaxDynamicSharedMemorySize, GEMM_SMEM);
    cudaFuncSetAttribute(gemm_pipe<1,0,0>, cudaFuncAttributeMaxDynamicSharedMemorySize, GEMM_SMEM);
    cudaFuncSetAttribute(fused_attn,       cudaFuncAttributeMaxDynamicSharedMemorySize, FUSED_SMEM);

    wprep<<<dim3(4096, 1, 7), 256>>>(Wq, Wk, Wv, Wo, Wi, Wo2, dist,
                                     WqT, WkT, WvT, WoT, WiT, Wo2T, dP);
    embed_ln<<<TOK, 256>>>(ids, inW, inb, tok, elg, elb, X);

    dim3 gG(DIM / 128, TOK / 128);
    dim3 gGi(FFI / 128, TOK / 128);
    dim3 gQD(QCOLS / 128, ROWSBH / 128);
    dim3 gA(SEQ / 128, BATCH * NHEAD);

    for (int l = 0; l < LNUM; l++) {
        const float* wqt  = WqT  + (size_t)l * DIM * DIM;
        const float* wkt  = WkT  + (size_t)l * DIM * DIM;
        const float* wvt  = WvT  + (size_t)l * DIM * DIM;
        const float* wot  = WoT  + (size_t)l * DIM * DIM;
        const float* wit  = WiT  + (size_t)l * FFI * DIM;
        const float* wo2t = Wo2T + (size_t)l * DIM * FFI;

        gemm_pipe<0,0,0><<<gG, 256, GEMM_SMEM>>>(X, wqt, bq + l * DIM, nullptr, Q,  DIM, DIM);
        gemm_pipe<0,0,0><<<gG, 256, GEMM_SMEM>>>(X, wkt, bk + l * DIM, nullptr, Kb, DIM, DIM);
        gemm_pipe<0,0,0><<<gG, 256, GEMM_SMEM>>>(X, wvt, bv + l * DIM, nullptr, V,  DIM, DIM);

        gemm_pipe<0,1,0><<<gQD, 256, GEMM_SMEM>>>(Q,  dP, nullptr, nullptr, QD, DHD, QCOLS);
        gemm_pipe<0,2,0><<<gQD, 256, GEMM_SMEM>>>(Kb, dP, nullptr, nullptr, KD, DHD, QCOLS);

        fused_attn<<<gA, 256, FUSED_SMEM>>>(Q, Kb, V, QD, KD, mask, CTX);

        gemm_pipe<0,0,1><<<gG, 256, GEMM_SMEM>>>(CTX, wot, bo + l * DIM, X, TMP, DIM, DIM);
        ln_w<<<TOK / 8, 256>>>(TMP, ln1g + l * DIM, ln1b + l * DIM, X);

        gemm_pipe<1,0,0><<<gGi, 256, GEMM_SMEM>>>(X, wit, bi + l * FFI, nullptr, Hb, DIM, FFI);
        gemm_pipe<0,0,1><<<gG, 256, GEMM_SMEM>>>(Hb, wo2t, bo2 + l * DIM, X, TMP, FFI, DIM);
        ln_w<<<TOK / 8, 256>>>(TMP, ln2g + l * DIM, ln2b + l * DIM,
                               (l == LNUM - 1) ? out : X);
    }
}